// round 1
// baseline (speedup 1.0000x reference)
#include <cuda_runtime.h>
#include <math.h>
#include <stdint.h>

// ---------------- problem constants ----------------
constexpr int NIMG = 4, IMGH = 224;
constexpr int C1 = 64,  H1 = 55;   // conv1 out (stride4 pad2 k11)
constexpr int P1 = 27;             // pool1 out
constexpr int C2 = 192, H2 = 27;   // conv2 out (pad2 k5)
constexpr int P2 = 13;             // pool2 out
constexpr int C3 = 384, H3 = 13;   // conv3 out (pad1 k3)
constexpr int NBOX = 1024, NCTX = 16, HEADS = 8, HID = 384;
constexpr int NVIS = 3456, BBH = 32, NOWN = 3488;       // 384*9 + 32
constexpr int KCOMB = HEADS * NOWN;                     // 27904
constexpr int NC2 = 2 * NOWN;                           // 6976
constexpr int NCLS = 10;

// ---------------- device scratch ----------------
__device__ float g_x1[NIMG*C1*H1*H1];
__device__ float g_p1[NIMG*C1*P1*P1];
__device__ float g_x2[NIMG*C2*H2*H2];
__device__ float g_p2[NIMG*C2*P2*P2];
__device__ float g_x3[NIMG*C3*H3*H3];
__device__ float g_own[(NBOX+1)*NOWN];     // visual | bbox_feat, +1 zero pad row
__device__ float g_lin[NBOX*BBH];
__device__ float g_uk[HEADS*NOWN];
__device__ float g_sk[(NBOX+1)*HEADS];
__device__ float g_wts[NBOX*HEADS*NCTX];
__device__ float g_ctx[(size_t)NBOX*KCOMB];   // 114 MB
__device__ float g_out1[NBOX*NOWN];
__device__ float g_comb[NBOX*NC2];
__device__ float g_h1[NBOX*NC2];
__device__ float g_mean[NC2];
__device__ float g_rstd[NC2];

__device__ __forceinline__ float* sel_buf(int s) {
    switch (s) {
        case 0: return g_lin;
        case 1: return g_out1;
        case 2: return g_h1;
        case 3: return g_own;
        case 4: return g_comb;
        case 5: return g_ctx;
    }
    return nullptr;
}

// ---------------- conv backbone ----------------
__global__ void conv1_k(const float* __restrict__ img, const float* __restrict__ w,
                        const float* __restrict__ b) {
    int p = blockIdx.x * blockDim.x + threadIdx.x;
    if (p >= H1*H1) return;
    int oc = blockIdx.y, n = blockIdx.z;
    int oh = p / H1, ow = p % H1;
    int ih0 = oh*4 - 2, iw0 = ow*4 - 2;
    float acc = b[oc];
    for (int ic = 0; ic < 3; ic++) {
        const float* ip = img + ((size_t)(n*3 + ic))*IMGH*IMGH;
        const float* wp = w + ((size_t)(oc*3 + ic))*121;
        #pragma unroll 1
        for (int kh = 0; kh < 11; kh++) {
            int ih = ih0 + kh;
            if (ih < 0 || ih >= IMGH) continue;
            for (int kw = 0; kw < 11; kw++) {
                int iw = iw0 + kw;
                if (iw < 0 || iw >= IMGH) continue;
                acc = fmaf(ip[ih*IMGH + iw], wp[kh*11 + kw], acc);
            }
        }
    }
    g_x1[((size_t)(n*C1 + oc)*H1 + oh)*H1 + ow] = fmaxf(acc, 0.f);
}

__global__ void maxpool_k(int stage) {
    const float* in = (stage == 0) ? g_x1 : g_x2;
    float* out = (stage == 0) ? g_p1 : g_p2;
    int NC = (stage == 0) ? NIMG*C1 : NIMG*C2;
    int H  = (stage == 0) ? H1 : H2;
    int Ho = (stage == 0) ? P1 : P2;
    int idx = blockIdx.x * blockDim.x + threadIdx.x;
    if (idx >= NC*Ho*Ho) return;
    int wo = idx % Ho, t = idx / Ho;
    int ho = t % Ho; int nc = t / Ho;
    const float* p = in + (size_t)nc*H*H;
    float m = -INFINITY;
    #pragma unroll
    for (int dh = 0; dh < 3; dh++)
        #pragma unroll
        for (int dw = 0; dw < 3; dw++)
            m = fmaxf(m, p[(ho*2 + dh)*H + wo*2 + dw]);
    out[idx] = m;
}

__global__ void conv2_k(const float* __restrict__ w, const float* __restrict__ b) {
    // grid (C2, NIMG), block 729
    int oc = blockIdx.x, n = blockIdx.y;
    int t = threadIdx.x;
    int oh = t / 27, ow = t % 27;
    __shared__ float tile[31*31];
    float acc = b[oc];
    for (int ic = 0; ic < C1; ic++) {
        __syncthreads();
        const float* ip = g_p1 + ((size_t)(n*C1 + ic))*27*27;
        for (int i = t; i < 31*31; i += 729) {
            int ih = i/31 - 2, iw = i%31 - 2;
            tile[i] = (ih >= 0 && ih < 27 && iw >= 0 && iw < 27) ? ip[ih*27 + iw] : 0.f;
        }
        __syncthreads();
        const float* wp = w + ((size_t)(oc*C1 + ic))*25;
        #pragma unroll
        for (int kh = 0; kh < 5; kh++)
            #pragma unroll
            for (int kw = 0; kw < 5; kw++)
                acc = fmaf(tile[(oh + kh)*31 + ow + kw], wp[kh*5 + kw], acc);
    }
    g_x2[((size_t)(n*C2 + oc)*27 + oh)*27 + ow] = fmaxf(acc, 0.f);
}

__global__ void conv3_k(const float* __restrict__ w, const float* __restrict__ b) {
    // grid (C3, NIMG), block 169
    int oc = blockIdx.x, n = blockIdx.y;
    int t = threadIdx.x;
    int oh = t / 13, ow = t % 13;
    __shared__ float tile[15*15];
    float acc = b[oc];
    for (int ic = 0; ic < C2; ic++) {
        __syncthreads();
        const float* ip = g_p2 + ((size_t)(n*C2 + ic))*13*13;
        for (int i = t; i < 15*15; i += 169) {
            int ih = i/15 - 1, iw = i%15 - 1;
            tile[i] = (ih >= 0 && ih < 13 && iw >= 0 && iw < 13) ? ip[ih*13 + iw] : 0.f;
        }
        __syncthreads();
        const float* wp = w + ((size_t)(oc*C2 + ic))*9;
        #pragma unroll
        for (int kh = 0; kh < 3; kh++)
            #pragma unroll
            for (int kw = 0; kw < 3; kw++)
                acc = fmaf(tile[(oh + kh)*15 + ow + kw], wp[kh*3 + kw], acc);
    }
    g_x3[((size_t)(n*C3 + oc)*13 + oh)*13 + ow] = acc;   // no relu
}

// ---------------- ROI max pool ----------------
__global__ void roi_k(const float* __restrict__ bb) {
    int n = blockIdx.x;
    int c = threadIdx.x;    // 384 channels
    const float sc = 13.0f / 224.0f;
    float b0 = bb[n*5 + 0], x1 = bb[n*5 + 1], y1 = bb[n*5 + 2],
          x2 = bb[n*5 + 3], y2 = bb[n*5 + 4];
    int img = (int)b0;
    int sw = (int)rintf(x1*sc), sh = (int)rintf(y1*sc);
    int ew = (int)rintf(x2*sc), eh = (int)rintf(y2*sc);
    float bw = fmaxf((float)(ew - sw + 1), 1.f) / 3.f;
    float bh = fmaxf((float)(eh - sh + 1), 1.f) / 3.f;
    const float* fp = g_x3 + ((size_t)img*C3 + c)*169;
    for (int ph = 0; ph < 3; ph++) {
        int h0 = min(max((int)floorf(ph*bh) + sh, 0), 13);
        int h1v = min(max((int)ceilf((ph + 1)*bh) + sh, 0), 13);
        for (int pw = 0; pw < 3; pw++) {
            int w0 = min(max((int)floorf(pw*bw) + sw, 0), 13);
            int w1 = min(max((int)ceilf((pw + 1)*bw) + sw, 0), 13);
            float m = -INFINITY;
            for (int h = h0; h < h1v; h++)
                for (int wv = w0; wv < w1; wv++)
                    m = fmaxf(m, fp[h*13 + wv]);
            if (m == -INFINITY) m = 0.f;
            g_own[(size_t)n*NOWN + c*9 + ph*3 + pw] = m;
        }
    }
}

// ---------------- bbox feature linear ----------------
__global__ void bboxlin_k(const float* __restrict__ bb, const float* __restrict__ w,
                          const float* __restrict__ bias) {
    int n = blockIdx.x * blockDim.x + threadIdx.x;
    if (n >= NBOX) return;
    float x1 = bb[n*5 + 1], y1 = bb[n*5 + 2], x2 = bb[n*5 + 3], y2 = bb[n*5 + 4];
    float wv = x2 - x1, hv = y2 - y1;
    float f[5] = {x1, y1, wv, hv, wv / hv};
    for (int j = 0; j < BBH; j++) {
        float a = bias[j];
        #pragma unroll
        for (int i = 0; i < 5; i++) a = fmaf(f[i], w[j*5 + i], a);
        g_lin[n*BBH + j] = a;
    }
}

// ---------------- batch-norm helpers ----------------
__global__ void colstats_k(int sel, int C) {
    // block (32,8): 32 columns per block
    int c = blockIdx.x * 32 + threadIdx.x;
    int ty = threadIdx.y;
    const float* X = sel_buf(sel);
    float s = 0.f, q = 0.f;
    if (c < C) {
        for (int n = ty; n < NBOX; n += 8) {
            float v = X[(size_t)n*C + c];
            s += v; q += v*v;
        }
    }
    __shared__ float ss[8][32], sq[8][32];
    ss[ty][threadIdx.x] = s; sq[ty][threadIdx.x] = q;
    __syncthreads();
    if (ty == 0 && c < C) {
        for (int r = 1; r < 8; r++) { s += ss[r][threadIdx.x]; q += sq[r][threadIdx.x]; }
        float m = s / NBOX;
        float v = q / NBOX - m*m;
        g_mean[c] = m;
        g_rstd[c] = rsqrtf(fmaxf(v, 0.f) + 1e-5f);
    }
}

__global__ void bnapply_k(int selS, int C, int selD, int dstStride, int colOff,
                          const float* __restrict__ gg, const float* __restrict__ bb) {
    int idx = blockIdx.x * blockDim.x + threadIdx.x;
    if (idx >= NBOX * C) return;
    int n = idx / C, c = idx % C;
    const float* X = sel_buf(selS);
    float v = (X[idx] - g_mean[c]) * g_rstd[c] * gg[c] + bb[c];
    sel_buf(selD)[(size_t)n*dstStride + colOff + c] = fmaxf(v, 0.f);
}

// ---------------- misc small kernels ----------------
__global__ void zerorow_k() {
    int t = blockIdx.x * blockDim.x + threadIdx.x;
    if (t < NOWN) g_own[(size_t)NBOX*NOWN + t] = 0.f;
}

__global__ void copyown_k() {
    int idx = blockIdx.x * blockDim.x + threadIdx.x;
    if (idx >= NBOX * NOWN) return;
    int n = idx / NOWN, c = idx % NOWN;
    g_comb[(size_t)n*NC2 + c] = g_own[(size_t)n*NOWN + c];
}

// ---------------- attention (algebraically collapsed) ----------------
// u_k[h,f] = sum_d Wk[h,d,f] * attn_w[h, HID + d]
__global__ void uk_k(const float* __restrict__ Wk, const float* __restrict__ attn_w) {
    int f = blockIdx.x * 256 + threadIdx.x;
    int h = blockIdx.y;
    if (f >= NOWN) return;
    float a = 0.f;
    const float* wp = Wk + (size_t)h*HID*NOWN + f;
    const float* ap = attn_w + h*2*HID + HID;
    for (int d = 0; d < HID; d++) a = fmaf(wp[(size_t)d*NOWN], ap[d], a);
    g_uk[h*NOWN + f] = a;
}

// s_k[b,h] = own_padded[b] . u_k[h]
__global__ void sk_k() {
    int bi = blockIdx.x, h = blockIdx.y, t = threadIdx.x;   // block 128
    const float* o = g_own + (size_t)bi*NOWN;
    const float* u = g_uk + (size_t)h*NOWN;
    float a = 0.f;
    for (int f = t; f < NOWN; f += 128) a = fmaf(o[f], u[f], a);
    #pragma unroll
    for (int off = 16; off; off >>= 1) a += __shfl_down_sync(0xffffffffu, a, off);
    __shared__ float s[4];
    if ((t & 31) == 0) s[t >> 5] = a;
    __syncthreads();
    if (t == 0) g_sk[bi*HEADS + h] = s[0] + s[1] + s[2] + s[3];
}

// softmax over 16 context entries per (n,h); constants-in-c all cancel
__global__ void wts_k(const int* __restrict__ ci) {
    int n = blockIdx.x, t = threadIdx.x;   // block 128: h = t/16, c = t%16
    int h = t / 16, c = t % 16;
    int idx = ci[n*NCTX + c];
    if (idx < 0) idx = NBOX;
    float v = g_sk[idx*HEADS + h];
    float mx = v;
    #pragma unroll
    for (int off = 8; off; off >>= 1) mx = fmaxf(mx, __shfl_xor_sync(0xffffffffu, mx, off, 16));
    float e = expf(v - mx);
    float s = e;
    #pragma unroll
    for (int off = 8; off; off >>= 1) s += __shfl_xor_sync(0xffffffffu, s, off, 16);
    g_wts[n*128 + t] = e / s;
}

// ctx[n, h*NOWN + f] = sum_c wts[n,h,c] * own_padded[ci2[n,c], f]
__global__ void ctx_k(const int* __restrict__ ci) {
    int n = blockIdx.x, t = threadIdx.x;   // block 256
    __shared__ float sw[128];
    __shared__ int sidx[16];
    if (t < 128) sw[t] = g_wts[n*128 + t];
    if (t < 16) { int v = ci[n*NCTX + t]; sidx[t] = (v < 0) ? NBOX : v; }
    __syncthreads();
    int id[16];
    #pragma unroll
    for (int c = 0; c < 16; c++) id[c] = sidx[c];
    for (int f = t; f < NOWN; f += 256) {
        float rv[16];
        #pragma unroll
        for (int c = 0; c < 16; c++) rv[c] = g_own[(size_t)id[c]*NOWN + f];
        #pragma unroll
        for (int h = 0; h < 8; h++) {
            float a = 0.f;
            #pragma unroll
            for (int c = 0; c < 16; c++) a = fmaf(sw[h*16 + c], rv[c], a);
            g_ctx[(size_t)n*KCOMB + (size_t)h*NOWN + f] = a;
        }
    }
}

// ---------------- SGEMM: C[M,N] = A[M,K] * B[N,K]^T + bias ----------------
__global__ void __launch_bounds__(256) sgemm_k(int selA, const float* __restrict__ B,
                        const float* __restrict__ bias, int selC,
                        int M, int N, int K) {
    __shared__ float As[8][128];
    __shared__ float Bs[8][128];
    const float* A = sel_buf(selA);
    float* C = sel_buf(selC);
    int tid = threadIdx.x;
    int tm = tid / 16, tn = tid % 16;
    int lr = tid >> 1;
    int lk = (tid & 1) * 4;
    int arow = blockIdx.y * 128 + lr;
    int brow = blockIdx.x * 128 + lr;
    const float* Aptr = A + (size_t)arow * K + lk;              // arow < M always (M=1024)
    const float* Bptr = (brow < N) ? (B + (size_t)brow * K + lk) : nullptr;
    float acc[8][8] = {};
    for (int k0 = 0; k0 < K; k0 += 8) {
        float4 av = *(const float4*)(Aptr + k0);
        float4 bv = make_float4(0.f, 0.f, 0.f, 0.f);
        if (Bptr) bv = *(const float4*)(Bptr + k0);
        As[lk + 0][lr] = av.x; As[lk + 1][lr] = av.y; As[lk + 2][lr] = av.z; As[lk + 3][lr] = av.w;
        Bs[lk + 0][lr] = bv.x; Bs[lk + 1][lr] = bv.y; Bs[lk + 2][lr] = bv.z; Bs[lk + 3][lr] = bv.w;
        __syncthreads();
        #pragma unroll
        for (int kk = 0; kk < 8; kk++) {
            float a[8], b[8];
            #pragma unroll
            for (int i = 0; i < 8; i++) a[i] = As[kk][tm*8 + i];
            #pragma unroll
            for (int j = 0; j < 8; j++) b[j] = Bs[kk][tn*8 + j];
            #pragma unroll
            for (int i = 0; i < 8; i++)
                #pragma unroll
                for (int j = 0; j < 8; j++) acc[i][j] = fmaf(a[i], b[j], acc[i][j]);
        }
        __syncthreads();
    }
    int row0 = blockIdx.y * 128 + tm*8;
    int col0 = blockIdx.x * 128 + tn*8;
    #pragma unroll
    for (int i = 0; i < 8; i++) {
        int r = row0 + i;
        #pragma unroll
        for (int j = 0; j < 8; j++) {
            int cc = col0 + j;
            if (r < M && cc < N)
                C[(size_t)r*N + cc] = acc[i][j] + (bias ? bias[cc] : 0.f);
        }
    }
}

// ---------------- final 10-class head ----------------
__global__ void final_k(const float* __restrict__ w2, const float* __restrict__ b2,
                        float* __restrict__ out) {
    int n = blockIdx.x, t = threadIdx.x;   // block 256
    float acc[NCLS] = {};
    const float* hp = g_h1 + (size_t)n*NC2;
    for (int k = t; k < NC2; k += 256) {
        float hv = hp[k];
        #pragma unroll
        for (int j = 0; j < NCLS; j++) acc[j] = fmaf(hv, w2[(size_t)j*NC2 + k], acc[j]);
    }
    __shared__ float red[256];
    for (int j = 0; j < NCLS; j++) {
        red[t] = acc[j];
        __syncthreads();
        for (int s = 128; s; s >>= 1) { if (t < s) red[t] += red[t + s]; __syncthreads(); }
        if (t == 0) out[n*NCLS + j] = red[0] + b2[j];
        __syncthreads();
    }
}

// ---------------- launch ----------------
extern "C" void kernel_launch(void* const* d_in, const int* in_sizes, int n_in,
                              void* d_out, int out_size) {
    const float* images  = (const float*)d_in[0];
    const float* bboxes  = (const float*)d_in[1];
    const int*   ctxidx  = (const int*)  d_in[2];
    const float* c1w = (const float*)d_in[3];
    const float* c1b = (const float*)d_in[4];
    const float* c2w = (const float*)d_in[5];
    const float* c2b = (const float*)d_in[6];
    const float* c3w = (const float*)d_in[7];
    const float* c3b = (const float*)d_in[8];
    const float* bbox_w = (const float*)d_in[9];
    const float* bbox_b = (const float*)d_in[10];
    const float* bn_bb_g = (const float*)d_in[11];
    const float* bn_bb_b = (const float*)d_in[12];
    // d_in[13] Wq, d_in[14] bq: dead (softmax constant cancellation)
    const float* Wk = (const float*)d_in[15];
    // d_in[16] bk: dead (constant in softmax axis)
    const float* attn_w = (const float*)d_in[17];
    // d_in[18] attn_b: dead
    const float* comb_w = (const float*)d_in[19];
    const float* comb_b = (const float*)d_in[20];
    const float* bn_cb_g = (const float*)d_in[21];
    const float* bn_cb_b = (const float*)d_in[22];
    const float* dec_w1 = (const float*)d_in[23];
    const float* dec_b1 = (const float*)d_in[24];
    const float* bn_dc_g = (const float*)d_in[25];
    const float* bn_dc_b = (const float*)d_in[26];
    const float* dec_w2 = (const float*)d_in[27];
    const float* dec_b2 = (const float*)d_in[28];
    float* out = (float*)d_out;

    zerorow_k<<<(NOWN + 255)/256, 256>>>();

    // backbone
    conv1_k<<<dim3((H1*H1 + 255)/256, C1, NIMG), 256>>>(images, c1w, c1b);
    maxpool_k<<<(NIMG*C1*P1*P1 + 255)/256, 256>>>(0);
    conv2_k<<<dim3(C2, NIMG), 729>>>(c2w, c2b);
    maxpool_k<<<(NIMG*C2*P2*P2 + 255)/256, 256>>>(1);
    conv3_k<<<dim3(C3, NIMG), 169>>>(c3w, c3b);

    // features
    roi_k<<<NBOX, C3>>>(bboxes);
    bboxlin_k<<<(NBOX + 255)/256, 256>>>(bboxes, bbox_w, bbox_b);
    colstats_k<<<1, dim3(32, 8)>>>(0, BBH);
    bnapply_k<<<(NBOX*BBH + 255)/256, 256>>>(0, BBH, 3, NOWN, NVIS, bn_bb_g, bn_bb_b);

    // attention (collapsed)
    uk_k<<<dim3((NOWN + 255)/256, HEADS), 256>>>(Wk, attn_w);
    sk_k<<<dim3(NBOX + 1, HEADS), 128>>>();
    wts_k<<<NBOX, 128>>>(ctxidx);
    ctx_k<<<NBOX, 256>>>(ctxidx);

    // comb GEMM + BN + concat
    sgemm_k<<<dim3((NOWN + 127)/128, (NBOX + 127)/128), 256>>>(5, comb_w, comb_b, 1,
                                                               NBOX, NOWN, KCOMB);
    colstats_k<<<NOWN/32, dim3(32, 8)>>>(1, NOWN);
    bnapply_k<<<(NBOX*NOWN + 255)/256, 256>>>(1, NOWN, 4, NC2, NOWN, bn_cb_g, bn_cb_b);
    copyown_k<<<(NBOX*NOWN + 255)/256, 256>>>();

    // decoder GEMM + BN
    sgemm_k<<<dim3((NC2 + 127)/128, (NBOX + 127)/128), 256>>>(4, dec_w1, dec_b1, 2,
                                                              NBOX, NC2, NC2);
    colstats_k<<<NC2/32, dim3(32, 8)>>>(2, NC2);
    bnapply_k<<<(NBOX*NC2 + 255)/256, 256>>>(2, NC2, 2, NC2, 0, bn_dc_g, bn_dc_b);

    final_k<<<NBOX, 256>>>(dec_w2, dec_b2, out);
}

// round 3
// speedup vs baseline: 1.2673x; 1.2673x over previous
#include <cuda_runtime.h>
#include <cuda_bf16.h>
#include <math.h>
#include <stdint.h>

// ---------------- problem constants ----------------
constexpr int NIMG = 4, IMGH = 224;
constexpr int C1 = 64,  H1 = 55;
constexpr int P1 = 27;
constexpr int C2 = 192, H2 = 27;
constexpr int P2 = 13;
constexpr int C3 = 384;
constexpr int NBOX = 1024, NCTX = 16, HEADS = 8, HID = 384;
constexpr int NVIS = 3456, BBH = 32, NOWN = 3488;
constexpr int KCOMB = HEADS * NOWN;          // 27904
constexpr int NC2 = 2 * NOWN;                // 6976
constexpr int NCLS = 10;
constexpr int KTRI_COMB = 3 * KCOMB;         // 83712 (mult of 32)
constexpr int KTRI_DEC  = 3 * NC2;           // 20928 (mult of 32)

// ---------------- device scratch (fp32) ----------------
__device__ float g_x1[NIMG*C1*H1*H1];
__device__ float g_p1[NIMG*C1*P1*P1];
__device__ float g_x2[NIMG*C2*H2*H2];
__device__ float g_p2[NIMG*C2*P2*P2];
__device__ float g_x3[NIMG*C3*13*13];
__device__ float g_own[(NBOX+1)*NOWN];
__device__ float g_lin[NBOX*BBH];
__device__ float g_uk[HEADS*NOWN];
__device__ float g_sk[(NBOX+1)*HEADS];
__device__ float g_wts[NBOX*HEADS*NCTX];
__device__ float g_out1[NBOX*NOWN];
__device__ float g_comb[NBOX*NC2];
__device__ float g_h1[NBOX*NC2];
__device__ float g_mean[NC2];
__device__ float g_rstd[NC2];

// ---------------- device scratch (bf16 triple-K) ----------------
__device__ __align__(128) __nv_bfloat16 g_ctx_tri[(size_t)NBOX * KTRI_COMB];
__device__ __align__(128) __nv_bfloat16 g_combA_tri[(size_t)NBOX * KTRI_DEC];
__device__ __align__(128) __nv_bfloat16 g_combw_tri[(size_t)NOWN * KTRI_COMB];
__device__ __align__(128) __nv_bfloat16 g_decw_tri[(size_t)NC2 * KTRI_DEC];

__device__ __forceinline__ float* sel_buf(int s) {
    switch (s) {
        case 0: return g_lin;
        case 1: return g_out1;
        case 2: return g_h1;
        case 3: return g_own;
        case 4: return g_comb;
    }
    return nullptr;
}
__device__ __forceinline__ __nv_bfloat16* sel_bf16(int s) {
    switch (s) {
        case 0: return g_ctx_tri;
        case 1: return g_combA_tri;
        case 2: return g_combw_tri;
        case 3: return g_decw_tri;
    }
    return nullptr;
}

// ---------------- PTX helpers (sm_80-compatible; no tcgen05) ----------------
__device__ __forceinline__ uint32_t smem_u32(const void* p) {
    uint32_t a;
    asm("{ .reg .u64 t; cvta.to.shared.u64 t, %1; cvt.u32.u64 %0, t; }" : "=r"(a) : "l"(p));
    return a;
}
__device__ __forceinline__ void cpa16(uint32_t dst, const void* src, int srcsz) {
    asm volatile("cp.async.cg.shared.global [%0], [%1], 16, %2;"
                 :: "r"(dst), "l"(src), "r"(srcsz) : "memory");
}
__device__ __forceinline__ void cpa_commit() {
    asm volatile("cp.async.commit_group;" ::: "memory");
}
__device__ __forceinline__ void cpa_wait1() {
    asm volatile("cp.async.wait_group 1;" ::: "memory");
}
__device__ __forceinline__ void ldm_x4(uint32_t& r0, uint32_t& r1, uint32_t& r2, uint32_t& r3,
                                       uint32_t addr) {
    asm volatile("ldmatrix.sync.aligned.m8n8.x4.shared.b16 {%0,%1,%2,%3}, [%4];"
                 : "=r"(r0), "=r"(r1), "=r"(r2), "=r"(r3) : "r"(addr));
}
__device__ __forceinline__ void mma_bf16(float* c, uint32_t a0, uint32_t a1, uint32_t a2,
                                         uint32_t a3, uint32_t b0, uint32_t b1) {
    asm volatile(
        "mma.sync.aligned.m16n8k16.row.col.f32.bf16.bf16.f32 "
        "{%0,%1,%2,%3}, {%4,%5,%6,%7}, {%8,%9}, {%0,%1,%2,%3};"
        : "+f"(c[0]), "+f"(c[1]), "+f"(c[2]), "+f"(c[3])
        : "r"(a0), "r"(a1), "r"(a2), "r"(a3), "r"(b0), "r"(b1));
}

// ---------------- conv backbone ----------------
__global__ void conv1_k(const float* __restrict__ img, const float* __restrict__ w,
                        const float* __restrict__ b) {
    int p = blockIdx.x * blockDim.x + threadIdx.x;
    if (p >= H1*H1) return;
    int oc = blockIdx.y, n = blockIdx.z;
    int oh = p / H1, ow = p % H1;
    int ih0 = oh*4 - 2, iw0 = ow*4 - 2;
    float acc = b[oc];
    for (int ic = 0; ic < 3; ic++) {
        const float* ip = img + ((size_t)(n*3 + ic))*IMGH*IMGH;
        const float* wp = w + ((size_t)(oc*3 + ic))*121;
        #pragma unroll 1
        for (int kh = 0; kh < 11; kh++) {
            int ih = ih0 + kh;
            if (ih < 0 || ih >= IMGH) continue;
            for (int kw = 0; kw < 11; kw++) {
                int iw = iw0 + kw;
                if (iw < 0 || iw >= IMGH) continue;
                acc = fmaf(ip[ih*IMGH + iw], wp[kh*11 + kw], acc);
            }
        }
    }
    g_x1[((size_t)(n*C1 + oc)*H1 + oh)*H1 + ow] = fmaxf(acc, 0.f);
}

__global__ void maxpool_k(int stage) {
    const float* in = (stage == 0) ? g_x1 : g_x2;
    float* out = (stage == 0) ? g_p1 : g_p2;
    int NC = (stage == 0) ? NIMG*C1 : NIMG*C2;
    int H  = (stage == 0) ? H1 : H2;
    int Ho = (stage == 0) ? P1 : P2;
    int idx = blockIdx.x * blockDim.x + threadIdx.x;
    if (idx >= NC*Ho*Ho) return;
    int wo = idx % Ho, t = idx / Ho;
    int ho = t % Ho; int nc = t / Ho;
    const float* p = in + (size_t)nc*H*H;
    float m = -INFINITY;
    #pragma unroll
    for (int dh = 0; dh < 3; dh++)
        #pragma unroll
        for (int dw = 0; dw < 3; dw++)
            m = fmaxf(m, p[(ho*2 + dh)*H + wo*2 + dw]);
    out[idx] = m;
}

// 4 output channels per block: input tile loads amortized 4x
__global__ void conv2_k(const float* __restrict__ w, const float* __restrict__ b) {
    int ocb = blockIdx.x * 4, n = blockIdx.y;   // grid (48, NIMG), block 729
    int t = threadIdx.x;
    int oh = t / 27, ow = t % 27;
    __shared__ float tile[31*31];
    __shared__ float ws[4*64*25];
    for (int i = t; i < 4*64*25; i += 729)
        ws[i] = w[(size_t)(ocb + i/(64*25))*64*25 + i%(64*25)];
    float acc[4] = {b[ocb], b[ocb+1], b[ocb+2], b[ocb+3]};
    for (int ic = 0; ic < C1; ic++) {
        __syncthreads();
        const float* ip = g_p1 + ((size_t)(n*C1 + ic))*27*27;
        for (int i = t; i < 31*31; i += 729) {
            int ih = i/31 - 2, iw = i%31 - 2;
            tile[i] = (ih >= 0 && ih < 27 && iw >= 0 && iw < 27) ? ip[ih*27 + iw] : 0.f;
        }
        __syncthreads();
        #pragma unroll
        for (int kh = 0; kh < 5; kh++)
            #pragma unroll
            for (int kw = 0; kw < 5; kw++) {
                float v = tile[(oh + kh)*31 + ow + kw];
                #pragma unroll
                for (int o = 0; o < 4; o++)
                    acc[o] = fmaf(v, ws[o*1600 + ic*25 + kh*5 + kw], acc[o]);
            }
    }
    #pragma unroll
    for (int o = 0; o < 4; o++)
        g_x2[((size_t)(n*C2 + ocb + o)*27 + oh)*27 + ow] = fmaxf(acc[o], 0.f);
}

__global__ void conv3_k(const float* __restrict__ w, const float* __restrict__ b) {
    int ocb = blockIdx.x * 4, n = blockIdx.y;   // grid (96, NIMG), block 169
    int t = threadIdx.x;
    int oh = t / 13, ow = t % 13;
    __shared__ float tile[15*15];
    float acc[4] = {b[ocb], b[ocb+1], b[ocb+2], b[ocb+3]};
    for (int ic = 0; ic < C2; ic++) {
        __syncthreads();
        const float* ip = g_p2 + ((size_t)(n*C2 + ic))*13*13;
        for (int i = t; i < 15*15; i += 169) {
            int ih = i/15 - 1, iw = i%15 - 1;
            tile[i] = (ih >= 0 && ih < 13 && iw >= 0 && iw < 13) ? ip[ih*13 + iw] : 0.f;
        }
        __syncthreads();
        #pragma unroll
        for (int kh = 0; kh < 3; kh++)
            #pragma unroll
            for (int kw = 0; kw < 3; kw++) {
                float v = tile[(oh + kh)*15 + ow + kw];
                #pragma unroll
                for (int o = 0; o < 4; o++)
                    acc[o] = fmaf(v, w[((size_t)(ocb+o)*C2 + ic)*9 + kh*3 + kw], acc[o]);
            }
    }
    #pragma unroll
    for (int o = 0; o < 4; o++)
        g_x3[((size_t)(n*C3 + ocb + o)*13 + oh)*13 + ow] = acc[o];
}

// ---------------- ROI max pool ----------------
__global__ void roi_k(const float* __restrict__ bb) {
    int n = blockIdx.x;
    int c = threadIdx.x;
    const float sc = 13.0f / 224.0f;
    float b0 = bb[n*5 + 0], x1 = bb[n*5 + 1], y1 = bb[n*5 + 2],
          x2 = bb[n*5 + 3], y2 = bb[n*5 + 4];
    int img = (int)b0;
    int sw = (int)rintf(x1*sc), sh = (int)rintf(y1*sc);
    int ew = (int)rintf(x2*sc), eh = (int)rintf(y2*sc);
    float bw = fmaxf((float)(ew - sw + 1), 1.f) / 3.f;
    float bh = fmaxf((float)(eh - sh + 1), 1.f) / 3.f;
    const float* fp = g_x3 + ((size_t)img*C3 + c)*169;
    for (int ph = 0; ph < 3; ph++) {
        int h0 = min(max((int)floorf(ph*bh) + sh, 0), 13);
        int h1v = min(max((int)ceilf((ph + 1)*bh) + sh, 0), 13);
        for (int pw = 0; pw < 3; pw++) {
            int w0 = min(max((int)floorf(pw*bw) + sw, 0), 13);
            int w1 = min(max((int)ceilf((pw + 1)*bw) + sw, 0), 13);
            float m = -INFINITY;
            for (int h = h0; h < h1v; h++)
                for (int wv = w0; wv < w1; wv++)
                    m = fmaxf(m, fp[h*13 + wv]);
            if (m == -INFINITY) m = 0.f;
            g_own[(size_t)n*NOWN + c*9 + ph*3 + pw] = m;
        }
    }
}

// ---------------- bbox feature linear ----------------
__global__ void bboxlin_k(const float* __restrict__ bb, const float* __restrict__ w,
                          const float* __restrict__ bias) {
    int n = blockIdx.x * blockDim.x + threadIdx.x;
    if (n >= NBOX) return;
    float x1 = bb[n*5 + 1], y1 = bb[n*5 + 2], x2 = bb[n*5 + 3], y2 = bb[n*5 + 4];
    float wv = x2 - x1, hv = y2 - y1;
    float f[5] = {x1, y1, wv, hv, wv / hv};
    for (int j = 0; j < BBH; j++) {
        float a = bias[j];
        #pragma unroll
        for (int i = 0; i < 5; i++) a = fmaf(f[i], w[j*5 + i], a);
        g_lin[n*BBH + j] = a;
    }
}

// ---------------- batch-norm helpers ----------------
__global__ void colstats_k(int sel, int C) {
    int c = blockIdx.x * 32 + threadIdx.x;
    int ty = threadIdx.y;
    const float* X = sel_buf(sel);
    float s = 0.f, q = 0.f;
    if (c < C) {
        for (int n = ty; n < NBOX; n += 8) {
            float v = X[(size_t)n*C + c];
            s += v; q += v*v;
        }
    }
    __shared__ float ss[8][32], sq[8][32];
    ss[ty][threadIdx.x] = s; sq[ty][threadIdx.x] = q;
    __syncthreads();
    if (ty == 0 && c < C) {
        for (int r = 1; r < 8; r++) { s += ss[r][threadIdx.x]; q += sq[r][threadIdx.x]; }
        float m = s / NBOX;
        float v = q / NBOX - m*m;
        g_mean[c] = m;
        g_rstd[c] = rsqrtf(fmaxf(v, 0.f) + 1e-5f);
    }
}

__global__ void bnapply_k(int selS, int C, int selD, int dstStride, int colOff,
                          const float* __restrict__ gg, const float* __restrict__ bb) {
    int idx = blockIdx.x * blockDim.x + threadIdx.x;
    if (idx >= NBOX * C) return;
    int n = idx / C, c = idx % C;
    const float* X = sel_buf(selS);
    float v = (X[idx] - g_mean[c]) * g_rstd[c] * gg[c] + bb[c];
    sel_buf(selD)[(size_t)n*dstStride + colOff + c] = fmaxf(v, 0.f);
}

// bn(out1)+relu -> dec A triple (pattern A: hi, hi, lo), cols NOWN..2*NOWN
__global__ void bnapply_tri_k(const float* __restrict__ gg, const float* __restrict__ bb) {
    int idx = blockIdx.x * blockDim.x + threadIdx.x;
    if (idx >= NBOX * NOWN) return;
    int n = idx / NOWN, c = idx % NOWN;
    float v = (g_out1[idx] - g_mean[c]) * g_rstd[c] * gg[c] + bb[c];
    v = fmaxf(v, 0.f);
    __nv_bfloat16 hi = __float2bfloat16(v);
    __nv_bfloat16 lo = __float2bfloat16(v - __bfloat162float(hi));
    size_t base = (size_t)n * KTRI_DEC;
    int col = NOWN + c;
    g_combA_tri[base + col] = hi;
    g_combA_tri[base + NC2 + col] = hi;
    g_combA_tri[base + 2*NC2 + col] = lo;
}

// own -> dec A triple (pattern A), cols 0..NOWN
__global__ void copyown_tri_k() {
    int idx = blockIdx.x * blockDim.x + threadIdx.x;
    if (idx >= NBOX * NOWN) return;
    int n = idx / NOWN, c = idx % NOWN;
    float v = g_own[(size_t)n*NOWN + c];
    __nv_bfloat16 hi = __float2bfloat16(v);
    __nv_bfloat16 lo = __float2bfloat16(v - __bfloat162float(hi));
    size_t base = (size_t)n * KTRI_DEC;
    g_combA_tri[base + c] = hi;
    g_combA_tri[base + NC2 + c] = hi;
    g_combA_tri[base + 2*NC2 + c] = lo;
}

// fp32 weights -> bf16 triple (pattern B: hi, lo, hi)
__global__ void cvt_tri_k(const float* __restrict__ src, int selD, size_t total, int K) {
    __nv_bfloat16* dst = sel_bf16(selD);
    for (size_t i = (size_t)blockIdx.x*blockDim.x + threadIdx.x; i < total;
         i += (size_t)gridDim.x*blockDim.x) {
        size_t r = i / (unsigned)K; int k = (int)(i - r*(unsigned)K);
        float x = src[i];
        __nv_bfloat16 hi = __float2bfloat16(x);
        __nv_bfloat16 lo = __float2bfloat16(x - __bfloat162float(hi));
        __nv_bfloat16* d = dst + r*(size_t)(3*K);
        d[k] = hi; d[(size_t)K + k] = lo; d[(size_t)2*K + k] = hi;
    }
}

// ---------------- misc ----------------
__global__ void zerorow_k() {
    int t = blockIdx.x * blockDim.x + threadIdx.x;
    if (t < NOWN) g_own[(size_t)NBOX*NOWN + t] = 0.f;
}

// ---------------- attention (collapsed) ----------------
__global__ void uk_k(const float* __restrict__ Wk, const float* __restrict__ attn_w) {
    int f = blockIdx.x * 256 + threadIdx.x;
    int h = blockIdx.y;
    if (f >= NOWN) return;
    float a = 0.f;
    const float* wp = Wk + (size_t)h*HID*NOWN + f;
    const float* ap = attn_w + h*2*HID + HID;
    for (int d = 0; d < HID; d++) a = fmaf(wp[(size_t)d*NOWN], ap[d], a);
    g_uk[h*NOWN + f] = a;
}

__global__ void sk_k() {
    int bi = blockIdx.x, h = blockIdx.y, t = threadIdx.x;
    const float* o = g_own + (size_t)bi*NOWN;
    const float* u = g_uk + (size_t)h*NOWN;
    float a = 0.f;
    for (int f = t; f < NOWN; f += 128) a = fmaf(o[f], u[f], a);
    #pragma unroll
    for (int off = 16; off; off >>= 1) a += __shfl_down_sync(0xffffffffu, a, off);
    __shared__ float s[4];
    if ((t & 31) == 0) s[t >> 5] = a;
    __syncthreads();
    if (t == 0) g_sk[bi*HEADS + h] = s[0] + s[1] + s[2] + s[3];
}

__global__ void wts_k(const int* __restrict__ ci) {
    int n = blockIdx.x, t = threadIdx.x;
    int c = t % 16;
    int idx = ci[n*NCTX + c];
    if (idx < 0) idx = NBOX;
    int h = t / 16;
    float v = g_sk[idx*HEADS + h];
    float mx = v;
    #pragma unroll
    for (int off = 8; off; off >>= 1) mx = fmaxf(mx, __shfl_xor_sync(0xffffffffu, mx, off, 16));
    float e = expf(v - mx);
    float s = e;
    #pragma unroll
    for (int off = 8; off; off >>= 1) s += __shfl_xor_sync(0xffffffffu, s, off, 16);
    g_wts[n*128 + t] = e / s;
}

// ctx written directly as bf16 triple (pattern A: hi, hi, lo)
__global__ void ctx_tri_k(const int* __restrict__ ci) {
    int n = blockIdx.x, t = threadIdx.x;
    __shared__ float sw[128];
    __shared__ int sidx[16];
    if (t < 128) sw[t] = g_wts[n*128 + t];
    if (t < 16) { int v = ci[n*NCTX + t]; sidx[t] = (v < 0) ? NBOX : v; }
    __syncthreads();
    int id[16];
    #pragma unroll
    for (int c = 0; c < 16; c++) id[c] = sidx[c];
    size_t base = (size_t)n * KTRI_COMB;
    for (int f = t; f < NOWN; f += 256) {
        float rv[16];
        #pragma unroll
        for (int c = 0; c < 16; c++) rv[c] = g_own[(size_t)id[c]*NOWN + f];
        #pragma unroll
        for (int h = 0; h < 8; h++) {
            float a = 0.f;
            #pragma unroll
            for (int c = 0; c < 16; c++) a = fmaf(sw[h*16 + c], rv[c], a);
            __nv_bfloat16 hi = __float2bfloat16(a);
            __nv_bfloat16 lo = __float2bfloat16(a - __bfloat162float(hi));
            size_t col = (size_t)h*NOWN + f;
            g_ctx_tri[base + col] = hi;
            g_ctx_tri[base + KCOMB + col] = hi;
            g_ctx_tri[base + 2*KCOMB + col] = lo;
        }
    }
}

// ---------------- HMMA bf16 GEMM: C[1024,N] = A[1024,Ktri] * B[N,Ktri]^T + bias ----------------
// Tile 128(M) x 256(N) x 32(K), 8 warps (2x4), warp tile 64x64.
// SMEM row = 32 bf16 = 64B = 4x16B units, swizzle: phys_c = c ^ ((row>>1)&3).
constexpr int GSTAGES = 3;
constexpr int GSTAGE_BYTES = 128*64 + 256*64;          // A 8KB + B 16KB = 24KB
constexpr int GEMM_SMEM = GSTAGES * GSTAGE_BYTES;      // 73728

__global__ void __launch_bounds__(256, 1) gemm_tri_k(int selA, int selB,
        const float* __restrict__ bias, int selC, int N, int Ktri) {
    extern __shared__ __align__(128) char smem[];
    uint32_t sb = smem_u32(smem);
    const __nv_bfloat16* A = sel_bf16(selA);
    const __nv_bfloat16* B = sel_bf16(selB);
    float* C = sel_buf(selC);
    const int tid = threadIdx.x, wid = tid >> 5, lid = tid & 31;
    const int m0 = blockIdx.y * 128, n0 = blockIdx.x * 256;
    const size_t KtriB = (size_t)Ktri * 2;
    const char* Abase = (const char*)A + (size_t)m0 * KtriB;
    const char* Bbase = (const char*)B;
    const int nch = Ktri >> 5;

    // loader indices: A 512 16B-units (2/thread), B 1024 (4/thread)
    auto fill = [&](int kc, int stage) {
        uint32_t sA = sb + stage*GSTAGE_BYTES;
        uint32_t sB = sA + 128*64;
        size_t kb = (size_t)kc * 64;
        #pragma unroll
        for (int i = 0; i < 2; i++) {
            int u = tid + i*256, r = u >> 2, c = u & 3;
            cpa16(sA + r*64 + ((c ^ ((r>>1)&3))<<4),
                  Abase + (size_t)r*KtriB + kb + c*16, 16);
        }
        #pragma unroll
        for (int i = 0; i < 4; i++) {
            int u = tid + i*256, r = u >> 2, c = u & 3;
            int gn = n0 + r;
            const char* src = Bbase + (size_t)min(gn, N-1)*KtriB + kb + c*16;
            cpa16(sB + r*64 + ((c ^ ((r>>1)&3))<<4), src, gn < N ? 16 : 0);
        }
    };

    float acc[4][8][4];
    #pragma unroll
    for (int i = 0; i < 4; i++)
        #pragma unroll
        for (int j = 0; j < 8; j++)
            #pragma unroll
            for (int v = 0; v < 4; v++) acc[i][j][v] = 0.f;

    for (int s = 0; s < GSTAGES-1; s++) { fill(s, s); cpa_commit(); }

    const int wmRow = (wid & 1) * 64;
    const int wnCol = (wid >> 1) * 64;
    const int r8 = lid & 7, which = lid >> 3;
    const int rowAdd = r8 + ((which & 1) << 3);     // +row within 16-tile
    const int colAdd = which >> 1;                  // +16B col (k+8)

    for (int kc = 0; kc < nch; kc++) {
        int fs = kc + GSTAGES - 1;
        if (fs < nch) fill(fs, fs % GSTAGES);
        cpa_commit();
        cpa_wait1();
        __syncthreads();
        uint32_t sA = sb + (kc % GSTAGES)*GSTAGE_BYTES;
        uint32_t sB = sA + 128*64;
        #pragma unroll
        for (int ks = 0; ks < 2; ks++) {
            uint32_t a[4][4];
            #pragma unroll
            for (int mi = 0; mi < 4; mi++) {
                int ar = wmRow + mi*16 + rowAdd;
                int ac = (ks << 1) + colAdd;
                ldm_x4(a[mi][0], a[mi][1], a[mi][2], a[mi][3],
                       sA + ar*64 + (((ac) ^ ((ar>>1)&3))<<4));
            }
            #pragma unroll
            for (int nt = 0; nt < 4; nt++) {
                uint32_t r0, r1, r2, r3;
                int br = wnCol + nt*16 + rowAdd;
                int bc = (ks << 1) + colAdd;
                ldm_x4(r0, r1, r2, r3, sB + br*64 + (((bc) ^ ((br>>1)&3))<<4));
                #pragma unroll
                for (int mi = 0; mi < 4; mi++) {
                    mma_bf16(acc[mi][nt*2],     a[mi][0], a[mi][1], a[mi][2], a[mi][3], r0, r2);
                    mma_bf16(acc[mi][nt*2 + 1], a[mi][0], a[mi][1], a[mi][2], a[mi][3], r1, r3);
                }
            }
        }
        __syncthreads();
    }

    // epilogue
    int g = lid >> 2, tq = lid & 3;
    #pragma unroll
    for (int mi = 0; mi < 4; mi++) {
        int row1 = m0 + wmRow + mi*16 + g;
        int row2 = row1 + 8;
        float* C1 = C + (size_t)row1 * N;
        float* C2 = C + (size_t)row2 * N;
        #pragma unroll
        for (int nj = 0; nj < 8; nj++) {
            int col = n0 + wnCol + nj*8 + tq*2;
            if (col < N) {
                float b0 = bias[col], b1 = bias[col + 1];
                C1[col]     = acc[mi][nj][0] + b0;
                C1[col + 1] = acc[mi][nj][1] + b1;
                C2[col]     = acc[mi][nj][2] + b0;
                C2[col + 1] = acc[mi][nj][3] + b1;
            }
        }
    }
}

// ---------------- final 10-class head ----------------
__global__ void final_k(const float* __restrict__ w2, const float* __restrict__ b2,
                        float* __restrict__ out) {
    int n = blockIdx.x, t = threadIdx.x;
    float acc[NCLS] = {};
    const float* hp = g_h1 + (size_t)n*NC2;
    for (int k = t; k < NC2; k += 256) {
        float hv = hp[k];
        #pragma unroll
        for (int j = 0; j < NCLS; j++) acc[j] = fmaf(hv, w2[(size_t)j*NC2 + k], acc[j]);
    }
    __shared__ float red[256];
    for (int j = 0; j < NCLS; j++) {
        red[t] = acc[j];
        __syncthreads();
        for (int s = 128; s; s >>= 1) { if (t < s) red[t] += red[t + s]; __syncthreads(); }
        if (t == 0) out[n*NCLS + j] = red[0] + b2[j];
        __syncthreads();
    }
}

// ---------------- launch ----------------
extern "C" void kernel_launch(void* const* d_in, const int* in_sizes, int n_in,
                              void* d_out, int out_size) {
    const float* images  = (const float*)d_in[0];
    const float* bboxes  = (const float*)d_in[1];
    const int*   ctxidx  = (const int*)  d_in[2];
    const float* c1w = (const float*)d_in[3];
    const float* c1b = (const float*)d_in[4];
    const float* c2w = (const float*)d_in[5];
    const float* c2b = (const float*)d_in[6];
    const float* c3w = (const float*)d_in[7];
    const float* c3b = (const float*)d_in[8];
    const float* bbox_w = (const float*)d_in[9];
    const float* bbox_b = (const float*)d_in[10];
    const float* bn_bb_g = (const float*)d_in[11];
    const float* bn_bb_b = (const float*)d_in[12];
    const float* Wk = (const float*)d_in[15];
    const float* attn_w = (const float*)d_in[17];
    const float* comb_w = (const float*)d_in[19];
    const float* comb_b = (const float*)d_in[20];
    const float* bn_cb_g = (const float*)d_in[21];
    const float* bn_cb_b = (const float*)d_in[22];
    const float* dec_w1 = (const float*)d_in[23];
    const float* dec_b1 = (const float*)d_in[24];
    const float* bn_dc_g = (const float*)d_in[25];
    const float* bn_dc_b = (const float*)d_in[26];
    const float* dec_w2 = (const float*)d_in[27];
    const float* dec_b2 = (const float*)d_in[28];
    float* out = (float*)d_out;

    cudaFuncSetAttribute(gemm_tri_k, cudaFuncAttributeMaxDynamicSharedMemorySize, GEMM_SMEM);

    zerorow_k<<<(NOWN + 255)/256, 256>>>();

    // weight conversions
    cvt_tri_k<<<18944, 256>>>(comb_w, 2, (size_t)NOWN*KCOMB, KCOMB);
    cvt_tri_k<<<18944, 256>>>(dec_w1, 3, (size_t)NC2*NC2, NC2);

    // backbone
    conv1_k<<<dim3((H1*H1 + 255)/256, C1, NIMG), 256>>>(images, c1w, c1b);
    maxpool_k<<<(NIMG*C1*P1*P1 + 255)/256, 256>>>(0);
    conv2_k<<<dim3(C2/4, NIMG), 729>>>(c2w, c2b);
    maxpool_k<<<(NIMG*C2*P2*P2 + 255)/256, 256>>>(1);
    conv3_k<<<dim3(C3/4, NIMG), 169>>>(c3w, c3b);

    // features
    roi_k<<<NBOX, C3>>>(bboxes);
    bboxlin_k<<<(NBOX + 255)/256, 256>>>(bboxes, bbox_w, bbox_b);
    colstats_k<<<1, dim3(32, 8)>>>(0, BBH);
    bnapply_k<<<(NBOX*BBH + 255)/256, 256>>>(0, BBH, 3, NOWN, NVIS, bn_bb_g, bn_bb_b);

    // attention (collapsed)
    uk_k<<<dim3((NOWN + 255)/256, HEADS), 256>>>(Wk, attn_w);
    sk_k<<<dim3(NBOX + 1, HEADS), 128>>>();
    wts_k<<<NBOX, 128>>>(ctxidx);
    ctx_tri_k<<<NBOX, 256>>>(ctxidx);
    copyown_tri_k<<<(NBOX*NOWN + 255)/256, 256>>>();

    // comb GEMM (HMMA bf16 3-split) + BN -> dec A triple
    gemm_tri_k<<<dim3((NOWN + 255)/256, 8), 256, GEMM_SMEM>>>(0, 2, comb_b, 1, NOWN, KTRI_COMB);
    colstats_k<<<NOWN/32, dim3(32, 8)>>>(1, NOWN);
    bnapply_tri_k<<<(NBOX*NOWN + 255)/256, 256>>>(bn_cb_g, bn_cb_b);

    // decoder GEMM + BN
    gemm_tri_k<<<dim3((NC2 + 255)/256, 8), 256, GEMM_SMEM>>>(1, 3, dec_b1, 4, NC2, KTRI_DEC);
    colstats_k<<<NC2/32, dim3(32, 8)>>>(4, NC2);
    bnapply_k<<<(NBOX*NC2 + 255)/256, 256>>>(4, NC2, 2, NC2, 0, bn_dc_g, bn_dc_b);

    final_k<<<NBOX, 256>>>(dec_w2, dec_b2, out);
}

// round 7
// speedup vs baseline: 2.1610x; 1.7052x over previous
#include <cuda_runtime.h>
#include <cuda_bf16.h>
#include <math.h>
#include <stdint.h>

// ---------------- problem constants ----------------
constexpr int NIMG = 4, IMGH = 224;
constexpr int C1 = 64,  H1 = 55;
constexpr int P1 = 27;
constexpr int C2 = 192, H2 = 27;
constexpr int P2 = 13;
constexpr int C3 = 384;
constexpr int NBOX = 1024, NCTX = 16, HEADS = 8, HID = 384;
constexpr int NVIS = 3456, BBH = 32, NOWN = 3488;
constexpr int KCOMB = HEADS * NOWN;          // 27904
constexpr int NC2 = 2 * NOWN;                // 6976
constexpr int NCLS = 10;
constexpr int KTRI_COMB = 3 * KCOMB;         // 83712
constexpr int KTRI_DEC  = 3 * NC2;           // 20928

// ---------------- device scratch (fp32) ----------------
__device__ float g_x1[NIMG*C1*H1*H1];
__device__ float g_p1[NIMG*C1*P1*P1];
__device__ float g_x2[NIMG*C2*H2*H2];
__device__ float g_p2[NIMG*C2*P2*P2];
__device__ float g_x3[NIMG*C3*13*13];
__device__ float g_own[(NBOX+1)*NOWN];
__device__ float g_lin[NBOX*BBH];
__device__ float g_uk[HEADS*NOWN];
__device__ float g_sk[(NBOX+1)*HEADS];
__device__ float g_wts[NBOX*HEADS*NCTX];
__device__ float g_out1[NBOX*NOWN];
__device__ float g_comb[NBOX*NC2];
__device__ float g_h1[NBOX*NC2];
__device__ float g_mean[NC2];
__device__ float g_rstd[NC2];

// ---------------- device scratch (bf16 triple-K) ----------------
__device__ __align__(128) __nv_bfloat16 g_ctx_tri[(size_t)NBOX * KTRI_COMB];
__device__ __align__(128) __nv_bfloat16 g_combA_tri[(size_t)NBOX * KTRI_DEC];
__device__ __align__(128) __nv_bfloat16 g_combw_tri[(size_t)NOWN * KTRI_COMB];
__device__ __align__(128) __nv_bfloat16 g_decw_tri[(size_t)NC2 * KTRI_DEC];

__device__ __forceinline__ float* sel_buf(int s) {
    switch (s) {
        case 0: return g_lin;
        case 1: return g_out1;
        case 2: return g_h1;
        case 3: return g_own;
        case 4: return g_comb;
    }
    return nullptr;
}
__device__ __forceinline__ __nv_bfloat16* sel_bf16(int s) {
    switch (s) {
        case 0: return g_ctx_tri;
        case 1: return g_combA_tri;
        case 2: return g_combw_tri;
        case 3: return g_decw_tri;
    }
    return nullptr;
}

// ---------------- PTX helpers (sm_80-compatible; no tcgen05) ----------------
__device__ __forceinline__ uint32_t smem_u32(const void* p) {
    uint32_t a;
    asm("{ .reg .u64 t; cvta.to.shared.u64 t, %1; cvt.u32.u64 %0, t; }" : "=r"(a) : "l"(p));
    return a;
}
__device__ __forceinline__ void cpa16(uint32_t dst, const void* src, int srcsz) {
    asm volatile("cp.async.cg.shared.global [%0], [%1], 16, %2;"
                 :: "r"(dst), "l"(src), "r"(srcsz) : "memory");
}
__device__ __forceinline__ void cpa_commit() {
    asm volatile("cp.async.commit_group;" ::: "memory");
}
__device__ __forceinline__ void cpa_wait2() {
    asm volatile("cp.async.wait_group 2;" ::: "memory");
}
__device__ __forceinline__ void ldm_x4(uint32_t& r0, uint32_t& r1, uint32_t& r2, uint32_t& r3,
                                       uint32_t addr) {
    asm volatile("ldmatrix.sync.aligned.m8n8.x4.shared.b16 {%0,%1,%2,%3}, [%4];"
                 : "=r"(r0), "=r"(r1), "=r"(r2), "=r"(r3) : "r"(addr));
}
__device__ __forceinline__ void mma_bf16(float* c, uint32_t a0, uint32_t a1, uint32_t a2,
                                         uint32_t a3, uint32_t b0, uint32_t b1) {
    asm volatile(
        "mma.sync.aligned.m16n8k16.row.col.f32.bf16.bf16.f32 "
        "{%0,%1,%2,%3}, {%4,%5,%6,%7}, {%8,%9}, {%0,%1,%2,%3};"
        : "+f"(c[0]), "+f"(c[1]), "+f"(c[2]), "+f"(c[3])
        : "r"(a0), "r"(a1), "r"(a2), "r"(a3), "r"(b0), "r"(b1));
}

// ---------------- conv backbone ----------------
// 4 output channels per block, weights staged in smem
__global__ void conv1_k(const float* __restrict__ img, const float* __restrict__ w,
                        const float* __restrict__ b) {
    // grid (12, 16, NIMG), block 256
    int ocb = blockIdx.y * 4, n = blockIdx.z;
    int tid = threadIdx.x;
    __shared__ float ws[4*363];
    for (int i = tid; i < 4*363; i += 256) ws[i] = w[(size_t)ocb*363 + i];
    __syncthreads();
    int p = blockIdx.x * 256 + tid;
    if (p >= H1*H1) return;
    int oh = p / H1, ow = p % H1;
    int ih0 = oh*4 - 2, iw0 = ow*4 - 2;
    float acc[4] = {b[ocb], b[ocb+1], b[ocb+2], b[ocb+3]};
    for (int ic = 0; ic < 3; ic++) {
        const float* ip = img + ((size_t)(n*3 + ic))*IMGH*IMGH;
        const float* wp = ws + ic*121;
        #pragma unroll 1
        for (int kh = 0; kh < 11; kh++) {
            int ih = ih0 + kh;
            if (ih < 0 || ih >= IMGH) continue;
            for (int kw = 0; kw < 11; kw++) {
                int iw = iw0 + kw;
                if (iw < 0 || iw >= IMGH) continue;
                float v = ip[ih*IMGH + iw];
                #pragma unroll
                for (int o = 0; o < 4; o++)
                    acc[o] = fmaf(v, wp[o*363 + kh*11 + kw], acc[o]);
            }
        }
    }
    #pragma unroll
    for (int o = 0; o < 4; o++)
        g_x1[((size_t)(n*C1 + ocb + o)*H1 + oh)*H1 + ow] = fmaxf(acc[o], 0.f);
}

__global__ void maxpool_k(int stage) {
    const float* in = (stage == 0) ? g_x1 : g_x2;
    float* out = (stage == 0) ? g_p1 : g_p2;
    int NC = (stage == 0) ? NIMG*C1 : NIMG*C2;
    int H  = (stage == 0) ? H1 : H2;
    int Ho = (stage == 0) ? P1 : P2;
    int idx = blockIdx.x * blockDim.x + threadIdx.x;
    if (idx >= NC*Ho*Ho) return;
    int wo = idx % Ho, t = idx / Ho;
    int ho = t % Ho; int nc = t / Ho;
    const float* p = in + (size_t)nc*H*H;
    float m = -INFINITY;
    #pragma unroll
    for (int dh = 0; dh < 3; dh++)
        #pragma unroll
        for (int dw = 0; dw < 3; dw++)
            m = fmaxf(m, p[(ho*2 + dh)*H + wo*2 + dw]);
    out[idx] = m;
}

__global__ void conv2_k(const float* __restrict__ w, const float* __restrict__ b) {
    int ocb = blockIdx.x * 4, n = blockIdx.y;   // grid (48, NIMG), block 729
    int t = threadIdx.x;
    int oh = t / 27, ow = t % 27;
    __shared__ float tile[31*31];
    __shared__ float ws[4*64*25];
    for (int i = t; i < 4*64*25; i += 729)
        ws[i] = w[(size_t)(ocb + i/(64*25))*64*25 + i%(64*25)];
    float acc[4] = {b[ocb], b[ocb+1], b[ocb+2], b[ocb+3]};
    for (int ic = 0; ic < C1; ic++) {
        __syncthreads();
        const float* ip = g_p1 + ((size_t)(n*C1 + ic))*27*27;
        for (int i = t; i < 31*31; i += 729) {
            int ih = i/31 - 2, iw = i%31 - 2;
            tile[i] = (ih >= 0 && ih < 27 && iw >= 0 && iw < 27) ? ip[ih*27 + iw] : 0.f;
        }
        __syncthreads();
        #pragma unroll
        for (int kh = 0; kh < 5; kh++)
            #pragma unroll
            for (int kw = 0; kw < 5; kw++) {
                float v = tile[(oh + kh)*31 + ow + kw];
                #pragma unroll
                for (int o = 0; o < 4; o++)
                    acc[o] = fmaf(v, ws[o*1600 + ic*25 + kh*5 + kw], acc[o]);
            }
    }
    #pragma unroll
    for (int o = 0; o < 4; o++)
        g_x2[((size_t)(n*C2 + ocb + o)*27 + oh)*27 + ow] = fmaxf(acc[o], 0.f);
}

__global__ void conv3_k(const float* __restrict__ w, const float* __restrict__ b) {
    int ocb = blockIdx.x * 4, n = blockIdx.y;   // grid (96, NIMG), block 169
    int t = threadIdx.x;
    int oh = t / 13, ow = t % 13;
    __shared__ float tile[15*15];
    float acc[4] = {b[ocb], b[ocb+1], b[ocb+2], b[ocb+3]};
    for (int ic = 0; ic < C2; ic++) {
        __syncthreads();
        const float* ip = g_p2 + ((size_t)(n*C2 + ic))*13*13;
        for (int i = t; i < 15*15; i += 169) {
            int ih = i/15 - 1, iw = i%15 - 1;
            tile[i] = (ih >= 0 && ih < 13 && iw >= 0 && iw < 13) ? ip[ih*13 + iw] : 0.f;
        }
        __syncthreads();
        #pragma unroll
        for (int kh = 0; kh < 3; kh++)
            #pragma unroll
            for (int kw = 0; kw < 3; kw++) {
                float v = tile[(oh + kh)*15 + ow + kw];
                #pragma unroll
                for (int o = 0; o < 4; o++)
                    acc[o] = fmaf(v, w[((size_t)(ocb+o)*C2 + ic)*9 + kh*3 + kw], acc[o]);
            }
    }
    #pragma unroll
    for (int o = 0; o < 4; o++)
        g_x3[((size_t)(n*C3 + ocb + o)*13 + oh)*13 + ow] = acc[o];
}

// ---------------- ROI max pool ----------------
__global__ void roi_k(const float* __restrict__ bb) {
    int n = blockIdx.x;
    int c = threadIdx.x;
    const float sc = 13.0f / 224.0f;
    float b0 = bb[n*5 + 0], x1 = bb[n*5 + 1], y1 = bb[n*5 + 2],
          x2 = bb[n*5 + 3], y2 = bb[n*5 + 4];
    int img = (int)b0;
    int sw = (int)rintf(x1*sc), sh = (int)rintf(y1*sc);
    int ew = (int)rintf(x2*sc), eh = (int)rintf(y2*sc);
    float bw = fmaxf((float)(ew - sw + 1), 1.f) / 3.f;
    float bh = fmaxf((float)(eh - sh + 1), 1.f) / 3.f;
    const float* fp = g_x3 + ((size_t)img*C3 + c)*169;
    for (int ph = 0; ph < 3; ph++) {
        int h0 = min(max((int)floorf(ph*bh) + sh, 0), 13);
        int h1v = min(max((int)ceilf((ph + 1)*bh) + sh, 0), 13);
        for (int pw = 0; pw < 3; pw++) {
            int w0 = min(max((int)floorf(pw*bw) + sw, 0), 13);
            int w1 = min(max((int)ceilf((pw + 1)*bw) + sw, 0), 13);
            float m = -INFINITY;
            for (int h = h0; h < h1v; h++)
                for (int wv = w0; wv < w1; wv++)
                    m = fmaxf(m, fp[h*13 + wv]);
            if (m == -INFINITY) m = 0.f;
            g_own[(size_t)n*NOWN + c*9 + ph*3 + pw] = m;
        }
    }
}

// ---------------- bbox feature linear ----------------
__global__ void bboxlin_k(const float* __restrict__ bb, const float* __restrict__ w,
                          const float* __restrict__ bias) {
    int n = blockIdx.x * blockDim.x + threadIdx.x;
    if (n >= NBOX) return;
    float x1 = bb[n*5 + 1], y1 = bb[n*5 + 2], x2 = bb[n*5 + 3], y2 = bb[n*5 + 4];
    float wv = x2 - x1, hv = y2 - y1;
    float f[5] = {x1, y1, wv, hv, wv / hv};
    for (int j = 0; j < BBH; j++) {
        float a = bias[j];
        #pragma unroll
        for (int i = 0; i < 5; i++) a = fmaf(f[i], w[j*5 + i], a);
        g_lin[n*BBH + j] = a;
    }
}

// ---------------- batch-norm helpers ----------------
__global__ void colstats_k(int sel, int C) {
    int c = blockIdx.x * 32 + threadIdx.x;
    int ty = threadIdx.y;
    const float* X = sel_buf(sel);
    float s = 0.f, q = 0.f;
    if (c < C) {
        for (int n = ty; n < NBOX; n += 8) {
            float v = X[(size_t)n*C + c];
            s += v; q += v*v;
        }
    }
    __shared__ float ss[8][32], sq[8][32];
    ss[ty][threadIdx.x] = s; sq[ty][threadIdx.x] = q;
    __syncthreads();
    if (ty == 0 && c < C) {
        for (int r = 1; r < 8; r++) { s += ss[r][threadIdx.x]; q += sq[r][threadIdx.x]; }
        float m = s / NBOX;
        float v = q / NBOX - m*m;
        g_mean[c] = m;
        g_rstd[c] = rsqrtf(fmaxf(v, 0.f) + 1e-5f);
    }
}

__global__ void bnapply_k(int selS, int C, int selD, int dstStride, int colOff,
                          const float* __restrict__ gg, const float* __restrict__ bb) {
    int idx = blockIdx.x * blockDim.x + threadIdx.x;
    if (idx >= NBOX * C) return;
    int n = idx / C, c = idx % C;
    const float* X = sel_buf(selS);
    float v = (X[idx] - g_mean[c]) * g_rstd[c] * gg[c] + bb[c];
    sel_buf(selD)[(size_t)n*dstStride + colOff + c] = fmaxf(v, 0.f);
}

// bn(out1)+relu -> dec A triple (pattern A: hi, hi, lo), cols NOWN..2*NOWN
__global__ void bnapply_tri_k(const float* __restrict__ gg, const float* __restrict__ bb) {
    int idx = blockIdx.x * blockDim.x + threadIdx.x;
    if (idx >= NBOX * NOWN) return;
    int n = idx / NOWN, c = idx % NOWN;
    float v = (g_out1[idx] - g_mean[c]) * g_rstd[c] * gg[c] + bb[c];
    v = fmaxf(v, 0.f);
    __nv_bfloat16 hi = __float2bfloat16(v);
    __nv_bfloat16 lo = __float2bfloat16(v - __bfloat162float(hi));
    size_t base = (size_t)n * KTRI_DEC;
    int col = NOWN + c;
    g_combA_tri[base + col] = hi;
    g_combA_tri[base + NC2 + col] = hi;
    g_combA_tri[base + 2*NC2 + col] = lo;
}

// own -> dec A triple (pattern A), cols 0..NOWN
__global__ void copyown_tri_k() {
    int idx = blockIdx.x * blockDim.x + threadIdx.x;
    if (idx >= NBOX * NOWN) return;
    int n = idx / NOWN, c = idx % NOWN;
    float v = g_own[(size_t)n*NOWN + c];
    __nv_bfloat16 hi = __float2bfloat16(v);
    __nv_bfloat16 lo = __float2bfloat16(v - __bfloat162float(hi));
    size_t base = (size_t)n * KTRI_DEC;
    g_combA_tri[base + c] = hi;
    g_combA_tri[base + NC2 + c] = hi;
    g_combA_tri[base + 2*NC2 + c] = lo;
}

// fp32 weights -> bf16 triple (pattern B: hi, lo, hi)
__global__ void cvt_tri_k(const float* __restrict__ src, int selD, size_t total, int K) {
    __nv_bfloat16* dst = sel_bf16(selD);
    for (size_t i = (size_t)blockIdx.x*blockDim.x + threadIdx.x; i < total;
         i += (size_t)gridDim.x*blockDim.x) {
        size_t r = i / (unsigned)K; int k = (int)(i - r*(unsigned)K);
        float x = src[i];
        __nv_bfloat16 hi = __float2bfloat16(x);
        __nv_bfloat16 lo = __float2bfloat16(x - __bfloat162float(hi));
        __nv_bfloat16* d = dst + r*(size_t)(3*K);
        d[k] = hi; d[(size_t)K + k] = lo; d[(size_t)2*K + k] = hi;
    }
}

// ---------------- misc ----------------
__global__ void zerorow_k() {
    int t = blockIdx.x * blockDim.x + threadIdx.x;
    if (t < NOWN) g_own[(size_t)NBOX*NOWN + t] = 0.f;
}

// ---------------- attention (collapsed) ----------------
__global__ void uk_k(const float* __restrict__ Wk, const float* __restrict__ attn_w) {
    int f = blockIdx.x * 256 + threadIdx.x;
    int h = blockIdx.y;
    if (f >= NOWN) return;
    float a = 0.f;
    const float* wp = Wk + (size_t)h*HID*NOWN + f;
    const float* ap = attn_w + h*2*HID + HID;
    for (int d = 0; d < HID; d++) a = fmaf(wp[(size_t)d*NOWN], ap[d], a);
    g_uk[h*NOWN + f] = a;
}

__global__ void sk_k() {
    int bi = blockIdx.x, h = blockIdx.y, t = threadIdx.x;
    const float* o = g_own + (size_t)bi*NOWN;
    const float* u = g_uk + (size_t)h*NOWN;
    float a = 0.f;
    for (int f = t; f < NOWN; f += 128) a = fmaf(o[f], u[f], a);
    #pragma unroll
    for (int off = 16; off; off >>= 1) a += __shfl_down_sync(0xffffffffu, a, off);
    __shared__ float s[4];
    if ((t & 31) == 0) s[t >> 5] = a;
    __syncthreads();
    if (t == 0) g_sk[bi*HEADS + h] = s[0] + s[1] + s[2] + s[3];
}

__global__ void wts_k(const int* __restrict__ ci) {
    int n = blockIdx.x, t = threadIdx.x;
    int c = t % 16;
    int idx = ci[n*NCTX + c];
    if (idx < 0) idx = NBOX;
    int h = t / 16;
    float v = g_sk[idx*HEADS + h];
    float mx = v;
    #pragma unroll
    for (int off = 8; off; off >>= 1) mx = fmaxf(mx, __shfl_xor_sync(0xffffffffu, mx, off, 16));
    float e = expf(v - mx);
    float s = e;
    #pragma unroll
    for (int off = 8; off; off >>= 1) s += __shfl_xor_sync(0xffffffffu, s, off, 16);
    g_wts[n*128 + t] = e / s;
}

// ctx written directly as bf16 triple (pattern A: hi, hi, lo)
__global__ void ctx_tri_k(const int* __restrict__ ci) {
    int n = blockIdx.x, t = threadIdx.x;
    __shared__ float sw[128];
    __shared__ int sidx[16];
    if (t < 128) sw[t] = g_wts[n*128 + t];
    if (t < 16) { int v = ci[n*NCTX + t]; sidx[t] = (v < 0) ? NBOX : v; }
    __syncthreads();
    int id[16];
    #pragma unroll
    for (int c = 0; c < 16; c++) id[c] = sidx[c];
    size_t base = (size_t)n * KTRI_COMB;
    for (int f = t; f < NOWN; f += 256) {
        float rv[16];
        #pragma unroll
        for (int c = 0; c < 16; c++) rv[c] = g_own[(size_t)id[c]*NOWN + f];
        #pragma unroll
        for (int h = 0; h < 8; h++) {
            float a = 0.f;
            #pragma unroll
            for (int c = 0; c < 16; c++) a = fmaf(sw[h*16 + c], rv[c], a);
            __nv_bfloat16 hi = __float2bfloat16(a);
            __nv_bfloat16 lo = __float2bfloat16(a - __bfloat162float(hi));
            size_t col = (size_t)h*NOWN + f;
            g_ctx_tri[base + col] = hi;
            g_ctx_tri[base + KCOMB + col] = hi;
            g_ctx_tri[base + 2*KCOMB + col] = lo;
        }
    }
}

// ---------------- HMMA bf16 GEMM: C[1024,N] = A[1024,Ktri] * B[N,Ktri]^T + bias ----------------
// Tile 128(M) x 128(N) x 32(K), 8 warps (4x2), warp tile 32x64, 4 stages, 2 CTAs/SM.
// SMEM row = 32 bf16 = 64B = 4x16B units, swizzle: phys_c = c ^ ((row>>1)&3).
constexpr int GSTAGES = 4;
constexpr int GSTAGE_BYTES = 128*64 + 128*64;          // A 8KB + B 8KB = 16KB
constexpr int GEMM_SMEM = GSTAGES * GSTAGE_BYTES;      // 65536

__global__ void __launch_bounds__(256, 2) gemm_tri_k(int selA, int selB,
        const float* __restrict__ bias, int selC, int N, int Ktri) {
    extern __shared__ __align__(128) char smem[];
    uint32_t sb = smem_u32(smem);
    const __nv_bfloat16* A = sel_bf16(selA);
    const __nv_bfloat16* B = sel_bf16(selB);
    float* C = sel_buf(selC);
    const int tid = threadIdx.x, wid = tid >> 5, lid = tid & 31;
    const int m0 = blockIdx.y * 128, n0 = blockIdx.x * 128;
    const size_t KtriB = (size_t)Ktri * 2;
    const char* Abase = (const char*)A + (size_t)m0 * KtriB;
    const char* Bbase = (const char*)B;
    const int nch = Ktri >> 5;

    // loader: A 512 16B-units (2/thread), B 512 (2/thread)
    auto fill = [&](int kc, int stage) {
        uint32_t sA = sb + stage*GSTAGE_BYTES;
        uint32_t sB = sA + 128*64;
        size_t kb = (size_t)kc * 64;
        #pragma unroll
        for (int i = 0; i < 2; i++) {
            int u = tid + i*256, r = u >> 2, c = u & 3;
            cpa16(sA + r*64 + ((c ^ ((r>>1)&3))<<4),
                  Abase + (size_t)r*KtriB + kb + c*16, 16);
        }
        #pragma unroll
        for (int i = 0; i < 2; i++) {
            int u = tid + i*256, r = u >> 2, c = u & 3;
            int gn = n0 + r;
            const char* src = Bbase + (size_t)min(gn, N-1)*KtriB + kb + c*16;
            cpa16(sB + r*64 + ((c ^ ((r>>1)&3))<<4), src, gn < N ? 16 : 0);
        }
    };

    float acc[2][8][4];
    #pragma unroll
    for (int i = 0; i < 2; i++)
        #pragma unroll
        for (int j = 0; j < 8; j++)
            #pragma unroll
            for (int v = 0; v < 4; v++) acc[i][j][v] = 0.f;

    for (int s = 0; s < GSTAGES-1; s++) { fill(s, s); cpa_commit(); }

    const int wmRow = (wid & 3) * 32;       // warp M offset
    const int wnCol = (wid >> 2) * 64;      // warp N offset
    const int r8 = lid & 7, which = lid >> 3;
    const int rowAdd = r8 + ((which & 1) << 3);
    const int colAdd = which >> 1;

    for (int kc = 0; kc < nch; kc++) {
        int fs = kc + GSTAGES - 1;
        if (fs < nch) fill(fs, fs & 3);
        cpa_commit();
        cpa_wait2();
        __syncthreads();
        uint32_t sA = sb + (kc & 3)*GSTAGE_BYTES;
        uint32_t sB = sA + 128*64;
        #pragma unroll
        for (int ks = 0; ks < 2; ks++) {
            uint32_t a[2][4];
            #pragma unroll
            for (int mi = 0; mi < 2; mi++) {
                int ar = wmRow + mi*16 + rowAdd;
                int ac = (ks << 1) + colAdd;
                ldm_x4(a[mi][0], a[mi][1], a[mi][2], a[mi][3],
                       sA + ar*64 + ((ac ^ ((ar>>1)&3))<<4));
            }
            #pragma unroll
            for (int nt = 0; nt < 4; nt++) {
                uint32_t r0, r1, r2, r3;
                int br = wnCol + nt*16 + rowAdd;
                int bc = (ks << 1) + colAdd;
                ldm_x4(r0, r1, r2, r3, sB + br*64 + ((bc ^ ((br>>1)&3))<<4));
                #pragma unroll
                for (int mi = 0; mi < 2; mi++) {
                    mma_bf16(acc[mi][nt*2],     a[mi][0], a[mi][1], a[mi][2], a[mi][3], r0, r2);
                    mma_bf16(acc[mi][nt*2 + 1], a[mi][0], a[mi][1], a[mi][2], a[mi][3], r1, r3);
                }
            }
        }
        __syncthreads();
    }

    // epilogue
    int g = lid >> 2, tq = lid & 3;
    #pragma unroll
    for (int mi = 0; mi < 2; mi++) {
        int row1 = m0 + wmRow + mi*16 + g;
        int row2 = row1 + 8;
        float* C1 = C + (size_t)row1 * N;
        float* C2 = C + (size_t)row2 * N;
        #pragma unroll
        for (int nj = 0; nj < 8; nj++) {
            int col = n0 + wnCol + nj*8 + tq*2;
            if (col < N) {
                float b0 = bias[col], b1 = bias[col + 1];
                C1[col]     = acc[mi][nj][0] + b0;
                C1[col + 1] = acc[mi][nj][1] + b1;
                C2[col]     = acc[mi][nj][2] + b0;
                C2[col + 1] = acc[mi][nj][3] + b1;
            }
        }
    }
}

// ---------------- final 10-class head ----------------
__global__ void final_k(const float* __restrict__ w2, const float* __restrict__ b2,
                        float* __restrict__ out) {
    int n = blockIdx.x, t = threadIdx.x;
    float acc[NCLS] = {};
    const float* hp = g_h1 + (size_t)n*NC2;
    for (int k = t; k < NC2; k += 256) {
        float hv = hp[k];
        #pragma unroll
        for (int j = 0; j < NCLS; j++) acc[j] = fmaf(hv, w2[(size_t)j*NC2 + k], acc[j]);
    }
    __shared__ float red[256];
    for (int j = 0; j < NCLS; j++) {
        red[t] = acc[j];
        __syncthreads();
        for (int s = 128; s; s >>= 1) { if (t < s) red[t] += red[t + s]; __syncthreads(); }
        if (t == 0) out[n*NCLS + j] = red[0] + b2[j];
        __syncthreads();
    }
}

// ---------------- launch ----------------
extern "C" void kernel_launch(void* const* d_in, const int* in_sizes, int n_in,
                              void* d_out, int out_size) {
    const float* images  = (const float*)d_in[0];
    const float* bboxes  = (const float*)d_in[1];
    const int*   ctxidx  = (const int*)  d_in[2];
    const float* c1w = (const float*)d_in[3];
    const float* c1b = (const float*)d_in[4];
    const float* c2w = (const float*)d_in[5];
    const float* c2b = (const float*)d_in[6];
    const float* c3w = (const float*)d_in[7];
    const float* c3b = (const float*)d_in[8];
    const float* bbox_w = (const float*)d_in[9];
    const float* bbox_b = (const float*)d_in[10];
    const float* bn_bb_g = (const float*)d_in[11];
    const float* bn_bb_b = (const float*)d_in[12];
    const float* Wk = (const float*)d_in[15];
    const float* attn_w = (const float*)d_in[17];
    const float* comb_w = (const float*)d_in[19];
    const float* comb_b = (const float*)d_in[20];
    const float* bn_cb_g = (const float*)d_in[21];
    const float* bn_cb_b = (const float*)d_in[22];
    const float* dec_w1 = (const float*)d_in[23];
    const float* dec_b1 = (const float*)d_in[24];
    const float* bn_dc_g = (const float*)d_in[25];
    const float* bn_dc_b = (const float*)d_in[26];
    const float* dec_w2 = (const float*)d_in[27];
    const float* dec_b2 = (const float*)d_in[28];
    float* out = (float*)d_out;

    cudaFuncSetAttribute(gemm_tri_k, cudaFuncAttributeMaxDynamicSharedMemorySize, GEMM_SMEM);

    zerorow_k<<<(NOWN + 255)/256, 256>>>();

    // weight conversions
    cvt_tri_k<<<18944, 256>>>(comb_w, 2, (size_t)NOWN*KCOMB, KCOMB);
    cvt_tri_k<<<18944, 256>>>(dec_w1, 3, (size_t)NC2*NC2, NC2);

    // backbone
    conv1_k<<<dim3(12, 16, NIMG), 256>>>(images, c1w, c1b);
    maxpool_k<<<(NIMG*C1*P1*P1 + 255)/256, 256>>>(0);
    conv2_k<<<dim3(C2/4, NIMG), 729>>>(c2w, c2b);
    maxpool_k<<<(NIMG*C2*P2*P2 + 255)/256, 256>>>(1);
    conv3_k<<<dim3(C3/4, NIMG), 169>>>(c3w, c3b);

    // features
    roi_k<<<NBOX, C3>>>(bboxes);
    bboxlin_k<<<(NBOX + 255)/256, 256>>>(bboxes, bbox_w, bbox_b);
    colstats_k<<<1, dim3(32, 8)>>>(0, BBH);
    bnapply_k<<<(NBOX*BBH + 255)/256, 256>>>(0, BBH, 3, NOWN, NVIS, bn_bb_g, bn_bb_b);

    // attention (collapsed)
    uk_k<<<dim3((NOWN + 255)/256, HEADS), 256>>>(Wk, attn_w);
    sk_k<<<dim3(NBOX + 1, HEADS), 128>>>();
    wts_k<<<NBOX, 128>>>(ctxidx);
    ctx_tri_k<<<NBOX, 256>>>(ctxidx);
    copyown_tri_k<<<(NBOX*NOWN + 255)/256, 256>>>();

    // comb GEMM (HMMA bf16 3-split) + BN -> dec A triple
    gemm_tri_k<<<dim3((NOWN + 127)/128, 8), 256, GEMM_SMEM>>>(0, 2, comb_b, 1, NOWN, KTRI_COMB);
    colstats_k<<<NOWN/32, dim3(32, 8)>>>(1, NOWN);
    bnapply_tri_k<<<(NBOX*NOWN + 255)/256, 256>>>(bn_cb_g, bn_cb_b);

    // decoder GEMM + BN
    gemm_tri_k<<<dim3((NC2 + 127)/128, 8), 256, GEMM_SMEM>>>(1, 3, dec_b1, 4, NC2, KTRI_DEC);
    colstats_k<<<NC2/32, dim3(32, 8)>>>(4, NC2);
    bnapply_k<<<(NBOX*NC2 + 255)/256, 256>>>(4, NC2, 2, NC2, 0, bn_dc_g, bn_dc_b);

    final_k<<<NBOX, 256>>>(dec_w2, dec_b2, out);
}

// round 8
// speedup vs baseline: 2.9510x; 1.3655x over previous
#include <cuda_runtime.h>
#include <cuda_fp16.h>
#include <math.h>
#include <stdint.h>

// ---------------- problem constants ----------------
constexpr int NIMG = 4, IMGH = 224;
constexpr int C1 = 64,  H1 = 55;
constexpr int P1 = 27;
constexpr int C2 = 192, H2 = 27;
constexpr int P2 = 13;
constexpr int C3 = 384;
constexpr int NBOX = 1024, NCTX = 16, HEADS = 8, HID = 384;
constexpr int NVIS = 3456, BBH = 32, NOWN = 3488;
constexpr int KCOMB = HEADS * NOWN;          // 27904
constexpr int NC2 = 2 * NOWN;                // 6976
constexpr int NCLS = 10;
constexpr int KDBL_COMB = 2 * KCOMB;         // 55808
constexpr int KDBL_DEC  = 2 * NC2;           // 13952

// ---------------- device scratch (fp32) ----------------
__device__ float g_x1[NIMG*C1*H1*H1];
__device__ float g_p1[NIMG*C1*P1*P1];
__device__ float g_x2[NIMG*C2*H2*H2];
__device__ float g_p2[NIMG*C2*P2*P2];
__device__ float g_x3[NIMG*C3*13*13];
__device__ float g_own[(NBOX+1)*NOWN];
__device__ float g_lin[NBOX*BBH];
__device__ float g_uk[HEADS*NOWN];
__device__ float g_sk[(NBOX+1)*HEADS];
__device__ float g_wts[NBOX*HEADS*NCTX];
__device__ float g_out1[NBOX*NOWN];
__device__ float g_comb[NBOX*NC2];
__device__ float g_h1[NBOX*NC2];
__device__ float g_mean[NC2];
__device__ float g_rstd[NC2];

// ---------------- device scratch (fp16) ----------------
// A operands: [hi(0..K) | lo(0..K)] per row (K-doubled). B operands: hi only.
__device__ __align__(128) __half g_ctx_dbl[(size_t)NBOX * KDBL_COMB];    // 114 MB
__device__ __align__(128) __half g_combA_dbl[(size_t)NBOX * KDBL_DEC];   //  29 MB
__device__ __align__(128) __half g_combw_h[(size_t)NOWN * KCOMB];        // 195 MB
__device__ __align__(128) __half g_decw_h[(size_t)NC2 * NC2];            //  97 MB

__device__ __forceinline__ float* sel_buf(int s) {
    switch (s) {
        case 0: return g_lin;
        case 1: return g_out1;
        case 2: return g_h1;
        case 3: return g_own;
        case 4: return g_comb;
    }
    return nullptr;
}
__device__ __forceinline__ __half* sel_half(int s) {
    switch (s) {
        case 0: return g_ctx_dbl;
        case 1: return g_combA_dbl;
        case 2: return g_combw_h;
        case 3: return g_decw_h;
    }
    return nullptr;
}

// ---------------- PTX helpers (sm_80-compatible; no tcgen05) ----------------
__device__ __forceinline__ uint32_t smem_u32(const void* p) {
    uint32_t a;
    asm("{ .reg .u64 t; cvta.to.shared.u64 t, %1; cvt.u32.u64 %0, t; }" : "=r"(a) : "l"(p));
    return a;
}
__device__ __forceinline__ void cpa16(uint32_t dst, const void* src, int srcsz) {
    asm volatile("cp.async.cg.shared.global [%0], [%1], 16, %2;"
                 :: "r"(dst), "l"(src), "r"(srcsz) : "memory");
}
__device__ __forceinline__ void cpa_commit() {
    asm volatile("cp.async.commit_group;" ::: "memory");
}
__device__ __forceinline__ void cpa_wait2() {
    asm volatile("cp.async.wait_group 2;" ::: "memory");
}
__device__ __forceinline__ void ldm_x4(uint32_t& r0, uint32_t& r1, uint32_t& r2, uint32_t& r3,
                                       uint32_t addr) {
    asm volatile("ldmatrix.sync.aligned.m8n8.x4.shared.b16 {%0,%1,%2,%3}, [%4];"
                 : "=r"(r0), "=r"(r1), "=r"(r2), "=r"(r3) : "r"(addr));
}
__device__ __forceinline__ void mma_f16(float* c, uint32_t a0, uint32_t a1, uint32_t a2,
                                        uint32_t a3, uint32_t b0, uint32_t b1) {
    asm volatile(
        "mma.sync.aligned.m16n8k16.row.col.f32.f16.f16.f32 "
        "{%0,%1,%2,%3}, {%4,%5,%6,%7}, {%8,%9}, {%0,%1,%2,%3};"
        : "+f"(c[0]), "+f"(c[1]), "+f"(c[2]), "+f"(c[3])
        : "r"(a0), "r"(a1), "r"(a2), "r"(a3), "r"(b0), "r"(b1));
}
__device__ __forceinline__ void split_h(float x, __half& hi, __half& lo) {
    hi = __float2half(x);
    lo = __float2half(x - __half2float(hi));
}

// ---------------- conv backbone ----------------
__global__ void conv1_k(const float* __restrict__ img, const float* __restrict__ w,
                        const float* __restrict__ b) {
    int ocb = blockIdx.y * 4, n = blockIdx.z;
    int tid = threadIdx.x;
    __shared__ float ws[4*363];
    for (int i = tid; i < 4*363; i += 256) ws[i] = w[(size_t)ocb*363 + i];
    __syncthreads();
    int p = blockIdx.x * 256 + tid;
    if (p >= H1*H1) return;
    int oh = p / H1, ow = p % H1;
    int ih0 = oh*4 - 2, iw0 = ow*4 - 2;
    float acc[4] = {b[ocb], b[ocb+1], b[ocb+2], b[ocb+3]};
    for (int ic = 0; ic < 3; ic++) {
        const float* ip = img + ((size_t)(n*3 + ic))*IMGH*IMGH;
        const float* wp = ws + ic*121;
        #pragma unroll 1
        for (int kh = 0; kh < 11; kh++) {
            int ih = ih0 + kh;
            if (ih < 0 || ih >= IMGH) continue;
            for (int kw = 0; kw < 11; kw++) {
                int iw = iw0 + kw;
                if (iw < 0 || iw >= IMGH) continue;
                float v = ip[ih*IMGH + iw];
                #pragma unroll
                for (int o = 0; o < 4; o++)
                    acc[o] = fmaf(v, wp[o*363 + kh*11 + kw], acc[o]);
            }
        }
    }
    #pragma unroll
    for (int o = 0; o < 4; o++)
        g_x1[((size_t)(n*C1 + ocb + o)*H1 + oh)*H1 + ow] = fmaxf(acc[o], 0.f);
}

__global__ void maxpool_k(int stage) {
    const float* in = (stage == 0) ? g_x1 : g_x2;
    float* out = (stage == 0) ? g_p1 : g_p2;
    int NC = (stage == 0) ? NIMG*C1 : NIMG*C2;
    int H  = (stage == 0) ? H1 : H2;
    int Ho = (stage == 0) ? P1 : P2;
    int idx = blockIdx.x * blockDim.x + threadIdx.x;
    if (idx >= NC*Ho*Ho) return;
    int wo = idx % Ho, t = idx / Ho;
    int ho = t % Ho; int nc = t / Ho;
    const float* p = in + (size_t)nc*H*H;
    float m = -INFINITY;
    #pragma unroll
    for (int dh = 0; dh < 3; dh++)
        #pragma unroll
        for (int dw = 0; dw < 3; dw++)
            m = fmaxf(m, p[(ho*2 + dh)*H + wo*2 + dw]);
    out[idx] = m;
}

__global__ void conv2_k(const float* __restrict__ w, const float* __restrict__ b) {
    int ocb = blockIdx.x * 4, n = blockIdx.y;
    int t = threadIdx.x;
    int oh = t / 27, ow = t % 27;
    __shared__ float tile[31*31];
    __shared__ float ws[4*64*25];
    for (int i = t; i < 4*64*25; i += 729)
        ws[i] = w[(size_t)(ocb + i/(64*25))*64*25 + i%(64*25)];
    float acc[4] = {b[ocb], b[ocb+1], b[ocb+2], b[ocb+3]};
    for (int ic = 0; ic < C1; ic++) {
        __syncthreads();
        const float* ip = g_p1 + ((size_t)(n*C1 + ic))*27*27;
        for (int i = t; i < 31*31; i += 729) {
            int ih = i/31 - 2, iw = i%31 - 2;
            tile[i] = (ih >= 0 && ih < 27 && iw >= 0 && iw < 27) ? ip[ih*27 + iw] : 0.f;
        }
        __syncthreads();
        #pragma unroll
        for (int kh = 0; kh < 5; kh++)
            #pragma unroll
            for (int kw = 0; kw < 5; kw++) {
                float v = tile[(oh + kh)*31 + ow + kw];
                #pragma unroll
                for (int o = 0; o < 4; o++)
                    acc[o] = fmaf(v, ws[o*1600 + ic*25 + kh*5 + kw], acc[o]);
            }
    }
    #pragma unroll
    for (int o = 0; o < 4; o++)
        g_x2[((size_t)(n*C2 + ocb + o)*27 + oh)*27 + ow] = fmaxf(acc[o], 0.f);
}

__global__ void conv3_k(const float* __restrict__ w, const float* __restrict__ b) {
    int ocb = blockIdx.x * 4, n = blockIdx.y;
    int t = threadIdx.x;
    int oh = t / 13, ow = t % 13;
    __shared__ float tile[15*15];
    float acc[4] = {b[ocb], b[ocb+1], b[ocb+2], b[ocb+3]};
    for (int ic = 0; ic < C2; ic++) {
        __syncthreads();
        const float* ip = g_p2 + ((size_t)(n*C2 + ic))*13*13;
        for (int i = t; i < 15*15; i += 169) {
            int ih = i/15 - 1, iw = i%15 - 1;
            tile[i] = (ih >= 0 && ih < 13 && iw >= 0 && iw < 13) ? ip[ih*13 + iw] : 0.f;
        }
        __syncthreads();
        #pragma unroll
        for (int kh = 0; kh < 3; kh++)
            #pragma unroll
            for (int kw = 0; kw < 3; kw++) {
                float v = tile[(oh + kh)*15 + ow + kw];
                #pragma unroll
                for (int o = 0; o < 4; o++)
                    acc[o] = fmaf(v, w[((size_t)(ocb+o)*C2 + ic)*9 + kh*3 + kw], acc[o]);
            }
    }
    #pragma unroll
    for (int o = 0; o < 4; o++)
        g_x3[((size_t)(n*C3 + ocb + o)*13 + oh)*13 + ow] = acc[o];
}

// ---------------- ROI max pool ----------------
__global__ void roi_k(const float* __restrict__ bb) {
    int n = blockIdx.x;
    int c = threadIdx.x;
    const float sc = 13.0f / 224.0f;
    float b0 = bb[n*5 + 0], x1 = bb[n*5 + 1], y1 = bb[n*5 + 2],
          x2 = bb[n*5 + 3], y2 = bb[n*5 + 4];
    int img = (int)b0;
    int sw = (int)rintf(x1*sc), sh = (int)rintf(y1*sc);
    int ew = (int)rintf(x2*sc), eh = (int)rintf(y2*sc);
    float bw = fmaxf((float)(ew - sw + 1), 1.f) / 3.f;
    float bh = fmaxf((float)(eh - sh + 1), 1.f) / 3.f;
    const float* fp = g_x3 + ((size_t)img*C3 + c)*169;
    for (int ph = 0; ph < 3; ph++) {
        int h0 = min(max((int)floorf(ph*bh) + sh, 0), 13);
        int h1v = min(max((int)ceilf((ph + 1)*bh) + sh, 0), 13);
        for (int pw = 0; pw < 3; pw++) {
            int w0 = min(max((int)floorf(pw*bw) + sw, 0), 13);
            int w1 = min(max((int)ceilf((pw + 1)*bw) + sw, 0), 13);
            float m = -INFINITY;
            for (int h = h0; h < h1v; h++)
                for (int wv = w0; wv < w1; wv++)
                    m = fmaxf(m, fp[h*13 + wv]);
            if (m == -INFINITY) m = 0.f;
            g_own[(size_t)n*NOWN + c*9 + ph*3 + pw] = m;
        }
    }
}

// ---------------- bbox feature linear ----------------
__global__ void bboxlin_k(const float* __restrict__ bb, const float* __restrict__ w,
                          const float* __restrict__ bias) {
    int n = blockIdx.x * blockDim.x + threadIdx.x;
    if (n >= NBOX) return;
    float x1 = bb[n*5 + 1], y1 = bb[n*5 + 2], x2 = bb[n*5 + 3], y2 = bb[n*5 + 4];
    float wv = x2 - x1, hv = y2 - y1;
    float f[5] = {x1, y1, wv, hv, wv / hv};
    for (int j = 0; j < BBH; j++) {
        float a = bias[j];
        #pragma unroll
        for (int i = 0; i < 5; i++) a = fmaf(f[i], w[j*5 + i], a);
        g_lin[n*BBH + j] = a;
    }
}

// ---------------- batch-norm helpers ----------------
__global__ void colstats_k(int sel, int C) {
    int c = blockIdx.x * 32 + threadIdx.x;
    int ty = threadIdx.y;
    const float* X = sel_buf(sel);
    float s = 0.f, q = 0.f;
    if (c < C) {
        for (int n = ty; n < NBOX; n += 8) {
            float v = X[(size_t)n*C + c];
            s += v; q += v*v;
        }
    }
    __shared__ float ss[8][32], sq[8][32];
    ss[ty][threadIdx.x] = s; sq[ty][threadIdx.x] = q;
    __syncthreads();
    if (ty == 0 && c < C) {
        for (int r = 1; r < 8; r++) { s += ss[r][threadIdx.x]; q += sq[r][threadIdx.x]; }
        float m = s / NBOX;
        float v = q / NBOX - m*m;
        g_mean[c] = m;
        g_rstd[c] = rsqrtf(fmaxf(v, 0.f) + 1e-5f);
    }
}

__global__ void bnapply_k(int selS, int C, int selD, int dstStride, int colOff,
                          const float* __restrict__ gg, const float* __restrict__ bb) {
    int idx = blockIdx.x * blockDim.x + threadIdx.x;
    if (idx >= NBOX * C) return;
    int n = idx / C, c = idx % C;
    const float* X = sel_buf(selS);
    float v = (X[idx] - g_mean[c]) * g_rstd[c] * gg[c] + bb[c];
    sel_buf(selD)[(size_t)n*dstStride + colOff + c] = fmaxf(v, 0.f);
}

// bn(out1)+relu -> dec A double (hi at NOWN+c, lo at NC2+NOWN+c)
__global__ void bnapply_dbl_k(const float* __restrict__ gg, const float* __restrict__ bb) {
    int idx = blockIdx.x * blockDim.x + threadIdx.x;
    if (idx >= NBOX * NOWN) return;
    int n = idx / NOWN, c = idx % NOWN;
    float v = (g_out1[idx] - g_mean[c]) * g_rstd[c] * gg[c] + bb[c];
    v = fmaxf(v, 0.f);
    __half hi, lo; split_h(v, hi, lo);
    size_t base = (size_t)n * KDBL_DEC;
    g_combA_dbl[base + NOWN + c] = hi;
    g_combA_dbl[base + NC2 + NOWN + c] = lo;
}

// own -> dec A double (hi at c, lo at NC2+c)
__global__ void copyown_dbl_k() {
    int idx = blockIdx.x * blockDim.x + threadIdx.x;
    if (idx >= NBOX * NOWN) return;
    int n = idx / NOWN, c = idx % NOWN;
    float v = g_own[(size_t)n*NOWN + c];
    __half hi, lo; split_h(v, hi, lo);
    size_t base = (size_t)n * KDBL_DEC;
    g_combA_dbl[base + c] = hi;
    g_combA_dbl[base + NC2 + c] = lo;
}

// fp32 weights -> fp16 hi only
__global__ void cvt_h_k(const float* __restrict__ src, int selD, size_t total) {
    __half* dst = sel_half(selD);
    for (size_t i = (size_t)blockIdx.x*blockDim.x + threadIdx.x; i < total;
         i += (size_t)gridDim.x*blockDim.x)
        dst[i] = __float2half(src[i]);
}

// ---------------- misc ----------------
__global__ void zerorow_k() {
    int t = blockIdx.x * blockDim.x + threadIdx.x;
    if (t < NOWN) g_own[(size_t)NBOX*NOWN + t] = 0.f;
}

// ---------------- attention (collapsed) ----------------
__global__ void uk_k(const float* __restrict__ Wk, const float* __restrict__ attn_w) {
    int f = blockIdx.x * 256 + threadIdx.x;
    int h = blockIdx.y;
    if (f >= NOWN) return;
    float a = 0.f;
    const float* wp = Wk + (size_t)h*HID*NOWN + f;
    const float* ap = attn_w + h*2*HID + HID;
    for (int d = 0; d < HID; d++) a = fmaf(wp[(size_t)d*NOWN], ap[d], a);
    g_uk[h*NOWN + f] = a;
}

__global__ void sk_k() {
    int bi = blockIdx.x, h = blockIdx.y, t = threadIdx.x;
    const float* o = g_own + (size_t)bi*NOWN;
    const float* u = g_uk + (size_t)h*NOWN;
    float a = 0.f;
    for (int f = t; f < NOWN; f += 128) a = fmaf(o[f], u[f], a);
    #pragma unroll
    for (int off = 16; off; off >>= 1) a += __shfl_down_sync(0xffffffffu, a, off);
    __shared__ float s[4];
    if ((t & 31) == 0) s[t >> 5] = a;
    __syncthreads();
    if (t == 0) g_sk[bi*HEADS + h] = s[0] + s[1] + s[2] + s[3];
}

__global__ void wts_k(const int* __restrict__ ci) {
    int n = blockIdx.x, t = threadIdx.x;
    int c = t % 16;
    int idx = ci[n*NCTX + c];
    if (idx < 0) idx = NBOX;
    int h = t / 16;
    float v = g_sk[idx*HEADS + h];
    float mx = v;
    #pragma unroll
    for (int off = 8; off; off >>= 1) mx = fmaxf(mx, __shfl_xor_sync(0xffffffffu, mx, off, 16));
    float e = expf(v - mx);
    float s = e;
    #pragma unroll
    for (int off = 8; off; off >>= 1) s += __shfl_xor_sync(0xffffffffu, s, off, 16);
    g_wts[n*128 + t] = e / s;
}

// ctx written directly as fp16 double (hi at col, lo at KCOMB+col)
__global__ void ctx_dbl_k(const int* __restrict__ ci) {
    int n = blockIdx.x, t = threadIdx.x;
    __shared__ float sw[128];
    __shared__ int sidx[16];
    if (t < 128) sw[t] = g_wts[n*128 + t];
    if (t < 16) { int v = ci[n*NCTX + t]; sidx[t] = (v < 0) ? NBOX : v; }
    __syncthreads();
    int id[16];
    #pragma unroll
    for (int c = 0; c < 16; c++) id[c] = sidx[c];
    size_t base = (size_t)n * KDBL_COMB;
    for (int f = t; f < NOWN; f += 256) {
        float rv[16];
        #pragma unroll
        for (int c = 0; c < 16; c++) rv[c] = g_own[(size_t)id[c]*NOWN + f];
        #pragma unroll
        for (int h = 0; h < 8; h++) {
            float a = 0.f;
            #pragma unroll
            for (int c = 0; c < 16; c++) a = fmaf(sw[h*16 + c], rv[c], a);
            __half hi, lo; split_h(a, hi, lo);
            size_t col = (size_t)h*NOWN + f;
            g_ctx_dbl[base + col] = hi;
            g_ctx_dbl[base + KCOMB + col] = lo;
        }
    }
}

// ---------------- HMMA fp16 GEMM: C[1024,N] = A[1024,Ka] * Bwrap[N,Kb]^T + bias ---------------
// A is K-doubled [hi|lo]; B is hi-only, K-index wraps (kc mod nchB).
// Tile 128x128x32, 8 warps (4x2), warp tile 32x64, 4 stages, 2 CTAs/SM.
constexpr int GSTAGES = 4;
constexpr int GSTAGE_BYTES = 128*64 + 128*64;          // 16KB
constexpr int GEMM_SMEM = GSTAGES * GSTAGE_BYTES;      // 65536

__global__ void __launch_bounds__(256, 2) gemm_dbl_k(int selA, int selB,
        const float* __restrict__ bias, int selC, int N, int Ka, int Kb) {
    extern __shared__ __align__(128) char smem[];
    uint32_t sb = smem_u32(smem);
    const __half* A = sel_half(selA);
    const __half* B = sel_half(selB);
    float* C = sel_buf(selC);
    const int tid = threadIdx.x, wid = tid >> 5, lid = tid & 31;
    const int m0 = blockIdx.y * 128, n0 = blockIdx.x * 128;
    const size_t KaB = (size_t)Ka * 2, KbB = (size_t)Kb * 2;
    const char* Abase = (const char*)A + (size_t)m0 * KaB;
    const char* Bbase = (const char*)B;
    const int nch = Ka >> 5;
    const int nchB = Kb >> 5;

    auto fill = [&](int kc, int stage) {
        uint32_t sA = sb + stage*GSTAGE_BYTES;
        uint32_t sB = sA + 128*64;
        size_t ka = (size_t)kc * 64;
        int kcb = (kc >= nchB) ? (kc - nchB) : kc;
        size_t kb = (size_t)kcb * 64;
        #pragma unroll
        for (int i = 0; i < 2; i++) {
            int u = tid + i*256, r = u >> 2, c = u & 3;
            cpa16(sA + r*64 + ((c ^ ((r>>1)&3))<<4),
                  Abase + (size_t)r*KaB + ka + c*16, 16);
        }
        #pragma unroll
        for (int i = 0; i < 2; i++) {
            int u = tid + i*256, r = u >> 2, c = u & 3;
            int gn = n0 + r;
            const char* src = Bbase + (size_t)min(gn, N-1)*KbB + kb + c*16;
            cpa16(sB + r*64 + ((c ^ ((r>>1)&3))<<4), src, gn < N ? 16 : 0);
        }
    };

    float acc[2][8][4];
    #pragma unroll
    for (int i = 0; i < 2; i++)
        #pragma unroll
        for (int j = 0; j < 8; j++)
            #pragma unroll
            for (int v = 0; v < 4; v++) acc[i][j][v] = 0.f;

    for (int s = 0; s < GSTAGES-1; s++) { fill(s, s); cpa_commit(); }

    const int wmRow = (wid & 3) * 32;
    const int wnCol = (wid >> 2) * 64;
    const int r8 = lid & 7, which = lid >> 3;
    const int rowAdd = r8 + ((which & 1) << 3);
    const int colAdd = which >> 1;

    for (int kc = 0; kc < nch; kc++) {
        int fs = kc + GSTAGES - 1;
        if (fs < nch) fill(fs, fs & 3);
        cpa_commit();
        cpa_wait2();
        __syncthreads();
        uint32_t sA = sb + (kc & 3)*GSTAGE_BYTES;
        uint32_t sB = sA + 128*64;
        #pragma unroll
        for (int ks = 0; ks < 2; ks++) {
            uint32_t a[2][4];
            #pragma unroll
            for (int mi = 0; mi < 2; mi++) {
                int ar = wmRow + mi*16 + rowAdd;
                int ac = (ks << 1) + colAdd;
                ldm_x4(a[mi][0], a[mi][1], a[mi][2], a[mi][3],
                       sA + ar*64 + ((ac ^ ((ar>>1)&3))<<4));
            }
            #pragma unroll
            for (int nt = 0; nt < 4; nt++) {
                uint32_t r0, r1, r2, r3;
                int br = wnCol + nt*16 + rowAdd;
                int bc = (ks << 1) + colAdd;
                ldm_x4(r0, r1, r2, r3, sB + br*64 + ((bc ^ ((br>>1)&3))<<4));
                #pragma unroll
                for (int mi = 0; mi < 2; mi++) {
                    mma_f16(acc[mi][nt*2],     a[mi][0], a[mi][1], a[mi][2], a[mi][3], r0, r2);
                    mma_f16(acc[mi][nt*2 + 1], a[mi][0], a[mi][1], a[mi][2], a[mi][3], r1, r3);
                }
            }
        }
        __syncthreads();
    }

    // epilogue
    int g = lid >> 2, tq = lid & 3;
    #pragma unroll
    for (int mi = 0; mi < 2; mi++) {
        int row1 = m0 + wmRow + mi*16 + g;
        int row2 = row1 + 8;
        float* C1 = C + (size_t)row1 * N;
        float* C2 = C + (size_t)row2 * N;
        #pragma unroll
        for (int nj = 0; nj < 8; nj++) {
            int col = n0 + wnCol + nj*8 + tq*2;
            if (col < N) {
                float b0 = bias[col], b1 = bias[col + 1];
                C1[col]     = acc[mi][nj][0] + b0;
                C1[col + 1] = acc[mi][nj][1] + b1;
                C2[col]     = acc[mi][nj][2] + b0;
                C2[col + 1] = acc[mi][nj][3] + b1;
            }
        }
    }
}

// ---------------- final 10-class head ----------------
__global__ void final_k(const float* __restrict__ w2, const float* __restrict__ b2,
                        float* __restrict__ out) {
    int n = blockIdx.x, t = threadIdx.x;
    float acc[NCLS] = {};
    const float* hp = g_h1 + (size_t)n*NC2;
    for (int k = t; k < NC2; k += 256) {
        float hv = hp[k];
        #pragma unroll
        for (int j = 0; j < NCLS; j++) acc[j] = fmaf(hv, w2[(size_t)j*NC2 + k], acc[j]);
    }
    __shared__ float red[256];
    for (int j = 0; j < NCLS; j++) {
        red[t] = acc[j];
        __syncthreads();
        for (int s = 128; s; s >>= 1) { if (t < s) red[t] += red[t + s]; __syncthreads(); }
        if (t == 0) out[n*NCLS + j] = red[0] + b2[j];
        __syncthreads();
    }
}

// ---------------- launch ----------------
extern "C" void kernel_launch(void* const* d_in, const int* in_sizes, int n_in,
                              void* d_out, int out_size) {
    const float* images  = (const float*)d_in[0];
    const float* bboxes  = (const float*)d_in[1];
    const int*   ctxidx  = (const int*)  d_in[2];
    const float* c1w = (const float*)d_in[3];
    const float* c1b = (const float*)d_in[4];
    const float* c2w = (const float*)d_in[5];
    const float* c2b = (const float*)d_in[6];
    const float* c3w = (const float*)d_in[7];
    const float* c3b = (const float*)d_in[8];
    const float* bbox_w = (const float*)d_in[9];
    const float* bbox_b = (const float*)d_in[10];
    const float* bn_bb_g = (const float*)d_in[11];
    const float* bn_bb_b = (const float*)d_in[12];
    const float* Wk = (const float*)d_in[15];
    const float* attn_w = (const float*)d_in[17];
    const float* comb_w = (const float*)d_in[19];
    const float* comb_b = (const float*)d_in[20];
    const float* bn_cb_g = (const float*)d_in[21];
    const float* bn_cb_b = (const float*)d_in[22];
    const float* dec_w1 = (const float*)d_in[23];
    const float* dec_b1 = (const float*)d_in[24];
    const float* bn_dc_g = (const float*)d_in[25];
    const float* bn_dc_b = (const float*)d_in[26];
    const float* dec_w2 = (const float*)d_in[27];
    const float* dec_b2 = (const float*)d_in[28];
    float* out = (float*)d_out;

    cudaFuncSetAttribute(gemm_dbl_k, cudaFuncAttributeMaxDynamicSharedMemorySize, GEMM_SMEM);

    zerorow_k<<<(NOWN + 255)/256, 256>>>();

    // weight conversions (hi only)
    cvt_h_k<<<18944, 256>>>(comb_w, 2, (size_t)NOWN*KCOMB);
    cvt_h_k<<<18944, 256>>>(dec_w1, 3, (size_t)NC2*NC2);

    // backbone
    conv1_k<<<dim3(12, 16, NIMG), 256>>>(images, c1w, c1b);
    maxpool_k<<<(NIMG*C1*P1*P1 + 255)/256, 256>>>(0);
    conv2_k<<<dim3(C2/4, NIMG), 729>>>(c2w, c2b);
    maxpool_k<<<(NIMG*C2*P2*P2 + 255)/256, 256>>>(1);
    conv3_k<<<dim3(C3/4, NIMG), 169>>>(c3w, c3b);

    // features
    roi_k<<<NBOX, C3>>>(bboxes);
    bboxlin_k<<<(NBOX + 255)/256, 256>>>(bboxes, bbox_w, bbox_b);
    colstats_k<<<1, dim3(32, 8)>>>(0, BBH);
    bnapply_k<<<(NBOX*BBH + 255)/256, 256>>>(0, BBH, 3, NOWN, NVIS, bn_bb_g, bn_bb_b);

    // attention (collapsed)
    uk_k<<<dim3((NOWN + 255)/256, HEADS), 256>>>(Wk, attn_w);
    sk_k<<<dim3(NBOX + 1, HEADS), 128>>>();
    wts_k<<<NBOX, 128>>>(ctxidx);
    ctx_dbl_k<<<NBOX, 256>>>(ctxidx);
    copyown_dbl_k<<<(NBOX*NOWN + 255)/256, 256>>>();

    // comb GEMM (HMMA fp16 2-split) + BN -> dec A double
    gemm_dbl_k<<<dim3((NOWN + 127)/128, 8), 256, GEMM_SMEM>>>(0, 2, comb_b, 1,
                                                              NOWN, KDBL_COMB, KCOMB);
    colstats_k<<<NOWN/32, dim3(32, 8)>>>(1, NOWN);
    bnapply_dbl_k<<<(NBOX*NOWN + 255)/256, 256>>>(bn_cb_g, bn_cb_b);

    // decoder GEMM + BN
    gemm_dbl_k<<<dim3((NC2 + 127)/128, 8), 256, GEMM_SMEM>>>(1, 3, dec_b1, 4,
                                                             NC2, KDBL_DEC, NC2);
    colstats_k<<<NC2/32, dim3(32, 8)>>>(4, NC2);
    bnapply_k<<<(NBOX*NC2 + 255)/256, 256>>>(4, NC2, 2, NC2, 0, bn_dc_g, bn_dc_b);

    final_k<<<NBOX, 256>>>(dec_w2, dec_b2, out);
}